// round 1
// baseline (speedup 1.0000x reference)
#include <cuda_runtime.h>
#include <cuda_bf16.h>
#include <math.h>

// Problem constants
#define BB 2
#define SS 2048
#define DD 1024
#define HH 16
#define HD 64
#define MTOT (BB*SS)       // 4096

// Scratch (allocation-free rule: __device__ globals)
__device__ float g_qkv[(size_t)BB*SS*3*DD];   // [B,S,3D]  48 MB
__device__ float g_att[(size_t)BB*SS*DD];     // [B,S,D]   16 MB

// ---------------------------------------------------------------------------
// Tiled SGEMM with bias: C[M,N] = A[M,K] @ B[K,N] + bias[N]
// 64x64 tile, K-step 16, 256 threads, 4x4 microtile per thread.
// All dims divisible by tiles (M=4096, N in {3072,1024}, K=1024).
// ---------------------------------------------------------------------------
#define GP 68   // padded row stride (keeps 16B alignment: 68*4=272B)

__global__ __launch_bounds__(256) void gemm_bias_kernel(
    const float* __restrict__ A, const float* __restrict__ B,
    const float* __restrict__ bias, float* __restrict__ C,
    int M, int N, int K)
{
    __shared__ float As[16 * GP];   // As[k][m]
    __shared__ float Bs[16 * GP];   // Bs[k][n]

    int tid = threadIdx.x;
    int ty = tid >> 4;          // 0..15
    int tx = tid & 15;          // 0..15
    int m0 = blockIdx.y * 64;
    int n0 = blockIdx.x * 64;

    // load indices
    int lm  = tid >> 2;         // 0..63
    int lk4 = (tid & 3) * 4;    // 0,4,8,12
    int lk  = tid >> 4;         // 0..15
    int ln4 = (tid & 15) * 4;   // 0..60

    float acc[4][4] = {};

    for (int k0 = 0; k0 < K; k0 += 16) {
        float4 a4 = *(const float4*)&A[(size_t)(m0 + lm) * K + k0 + lk4];
        As[(lk4 + 0) * GP + lm] = a4.x;
        As[(lk4 + 1) * GP + lm] = a4.y;
        As[(lk4 + 2) * GP + lm] = a4.z;
        As[(lk4 + 3) * GP + lm] = a4.w;
        float4 b4 = *(const float4*)&B[(size_t)(k0 + lk) * N + n0 + ln4];
        *(float4*)&Bs[lk * GP + ln4] = b4;
        __syncthreads();

        #pragma unroll
        for (int k = 0; k < 16; k++) {
            float4 ra = *(const float4*)&As[k * GP + ty * 4];
            float4 rb = *(const float4*)&Bs[k * GP + tx * 4];
            float aR[4] = {ra.x, ra.y, ra.z, ra.w};
            float bR[4] = {rb.x, rb.y, rb.z, rb.w};
            #pragma unroll
            for (int i = 0; i < 4; i++)
                #pragma unroll
                for (int j = 0; j < 4; j++)
                    acc[i][j] = fmaf(aR[i], bR[j], acc[i][j]);
        }
        __syncthreads();
    }

    float4 bb = *(const float4*)&bias[n0 + tx * 4];
    #pragma unroll
    for (int i = 0; i < 4; i++) {
        float4 v;
        v.x = acc[i][0] + bb.x;
        v.y = acc[i][1] + bb.y;
        v.z = acc[i][2] + bb.z;
        v.w = acc[i][3] + bb.w;
        *(float4*)&C[(size_t)(m0 + ty * 4 + i) * N + n0 + tx * 4] = v;
    }
}

// ---------------------------------------------------------------------------
// Flash-attention (fp32, causal). One block per (q-tile 64, head, batch).
// Online softmax with 64-key blocks. Q/K/V come from g_qkv strided views.
// ---------------------------------------------------------------------------
#define TQ 64
#define TK 64
#define AP 68   // padded stride (272B, 16B aligned)

__global__ __launch_bounds__(256) void attn_kernel(
    const float* __restrict__ qkv, float* __restrict__ out)
{
    extern __shared__ float sm[];
    float* Qs  = sm;                 // TQ * AP
    float* Ks  = Qs + TQ * AP;       // TK * AP
    float* Vs  = Ks + TK * AP;       // TK * AP
    float* Ss  = Vs + TK * AP;       // TQ * AP
    float* mrow = Ss + TQ * AP;      // TQ
    float* lrow = mrow + TQ;         // TQ
    float* arow = lrow + TQ;         // TQ
    float* red  = arow + TQ;         // 4 * TQ

    int qt = blockIdx.x;   // 0..31
    int h  = blockIdx.y;   // 0..15
    int b  = blockIdx.z;   // 0..1
    int tid = threadIdx.x;
    int ty = tid >> 4, tx = tid & 15;
    int qbase = qt * TQ;

    const size_t rstride = 3 * DD;   // row stride of qkv in floats
    const float* qptr0 = qkv + ((size_t)b * SS + qbase) * rstride + h * HD;

    // load Q tile
    for (int i = tid; i < TQ * HD; i += 256) {
        int r = i >> 6, d = i & 63;
        Qs[r * AP + d] = qptr0[(size_t)r * rstride + d];
    }
    if (tid < TQ) { mrow[tid] = -1e30f; lrow[tid] = 0.0f; }
    float O[4][4] = {};
    const float scale = 0.125f;  // 1/sqrt(64)
    __syncthreads();

    int row = tid & 63;
    int seg = tid >> 6;      // 0..3, 16 cols each

    for (int kb = 0; kb <= qt; kb++) {
        int kbase = kb * TK;
        const float* kp = qkv + ((size_t)b * SS + kbase) * rstride + DD + h * HD;
        const float* vp = kp + DD;
        for (int i = tid; i < TK * HD; i += 256) {
            int r = i >> 6, d = i & 63;
            Ks[r * AP + d] = kp[(size_t)r * rstride + d];
            Vs[r * AP + d] = vp[(size_t)r * rstride + d];
        }
        __syncthreads();

        // S = scale * Q @ K^T (+ causal mask on diagonal block)
        float acc[4][4] = {};
        #pragma unroll 8
        for (int d = 0; d < HD; d++) {
            float rq[4], rk[4];
            #pragma unroll
            for (int i = 0; i < 4; i++) rq[i] = Qs[(ty * 4 + i) * AP + d];
            #pragma unroll
            for (int j = 0; j < 4; j++) rk[j] = Ks[(tx * 4 + j) * AP + d];
            #pragma unroll
            for (int i = 0; i < 4; i++)
                #pragma unroll
                for (int j = 0; j < 4; j++)
                    acc[i][j] = fmaf(rq[i], rk[j], acc[i][j]);
        }
        bool diag = (kb == qt);
        #pragma unroll
        for (int i = 0; i < 4; i++) {
            #pragma unroll
            for (int j = 0; j < 4; j++) {
                float s = acc[i][j] * scale;
                if (diag && (tx * 4 + j) > (ty * 4 + i)) s = -1e30f;
                Ss[(ty * 4 + i) * AP + tx * 4 + j] = s;
            }
        }
        __syncthreads();

        // row max (4 partials per row)
        float pm = -1e30f;
        #pragma unroll
        for (int c = 0; c < 16; c++)
            pm = fmaxf(pm, Ss[row * AP + seg * 16 + c]);
        red[seg * 64 + row] = pm;
        __syncthreads();
        if (seg == 0) {
            float mo = mrow[row];
            float mn = fmaxf(fmaxf(red[row], red[64 + row]),
                             fmaxf(red[128 + row], red[192 + row]));
            mn = fmaxf(mo, mn);
            float a = __expf(mo - mn);
            mrow[row] = mn;
            arow[row] = a;
            lrow[row] *= a;
        }
        __syncthreads();

        // P = exp(S - m), partial row sums
        float mn = mrow[row];
        float ps = 0.0f;
        #pragma unroll
        for (int c = 0; c < 16; c++) {
            float p = __expf(Ss[row * AP + seg * 16 + c] - mn);
            Ss[row * AP + seg * 16 + c] = p;
            ps += p;
        }
        red[seg * 64 + row] = ps;
        __syncthreads();
        if (seg == 0)
            lrow[row] += red[row] + red[64 + row] + red[128 + row] + red[192 + row];

        // O = O*alpha + P @ V
        float al[4];
        #pragma unroll
        for (int i = 0; i < 4; i++) al[i] = arow[ty * 4 + i];
        #pragma unroll
        for (int i = 0; i < 4; i++)
            #pragma unroll
            for (int j = 0; j < 4; j++)
                O[i][j] *= al[i];
        #pragma unroll 8
        for (int jk = 0; jk < TK; jk++) {
            float rp[4];
            #pragma unroll
            for (int i = 0; i < 4; i++) rp[i] = Ss[(ty * 4 + i) * AP + jk];
            float4 rv4 = *(const float4*)&Vs[jk * AP + tx * 4];
            float rv[4] = {rv4.x, rv4.y, rv4.z, rv4.w};
            #pragma unroll
            for (int i = 0; i < 4; i++)
                #pragma unroll
                for (int j = 0; j < 4; j++)
                    O[i][j] = fmaf(rp[i], rv[j], O[i][j]);
        }
        __syncthreads();   // protects Ks/Vs/Ss for next iter; publishes lrow
    }

    // finalize: divide by l, write [B,S,D] layout
    #pragma unroll
    for (int i = 0; i < 4; i++) {
        float inv = 1.0f / lrow[ty * 4 + i];
        float4 v;
        v.x = O[i][0] * inv;
        v.y = O[i][1] * inv;
        v.z = O[i][2] * inv;
        v.w = O[i][3] * inv;
        size_t orow = (size_t)b * SS + qbase + ty * 4 + i;
        *(float4*)&out[orow * DD + h * HD + tx * 4] = v;
    }
}

// ---------------------------------------------------------------------------
// Launch
// ---------------------------------------------------------------------------
extern "C" void kernel_launch(void* const* d_in, const int* in_sizes, int n_in,
                              void* d_out, int out_size)
{
    const float* x     = (const float*)d_in[0];
    const float* Wqkv  = (const float*)d_in[1];
    const float* bqkv  = (const float*)d_in[2];
    const float* Wproj = (const float*)d_in[3];
    const float* bproj = (const float*)d_in[4];
    float* out = (float*)d_out;

    float *qkv, *att;
    cudaGetSymbolAddress((void**)&qkv, g_qkv);
    cudaGetSymbolAddress((void**)&att, g_att);

    dim3 blk(256);

    // 1) QKV projection: [4096,1024] @ [1024,3072]
    gemm_bias_kernel<<<dim3(3 * DD / 64, MTOT / 64), blk>>>(
        x, Wqkv, bqkv, qkv, MTOT, 3 * DD, DD);

    // 2) causal flash attention
    size_t smem = (size_t)(4 * TQ * AP + 3 * TQ + 4 * TQ) * sizeof(float);
    cudaFuncSetAttribute(attn_kernel,
                         cudaFuncAttributeMaxDynamicSharedMemorySize,
                         (int)smem);
    attn_kernel<<<dim3(SS / TQ, HH, BB), blk, smem>>>(qkv, att);

    // 3) output projection: [4096,1024] @ [1024,1024]
    gemm_bias_kernel<<<dim3(DD / 64, MTOT / 64), blk>>>(
        att, Wproj, bproj, out, MTOT, DD, DD);
}

// round 3
// speedup vs baseline: 1.4835x; 1.4835x over previous
#include <cuda_runtime.h>
#include <cuda_bf16.h>
#include <math.h>
#include <stdint.h>

// Problem constants
#define BB 2
#define SS 2048
#define DD 1024
#define HH 16
#define HD 64
#define MTOT (BB*SS)       // 4096

// Scratch (allocation-free rule: __device__ globals)
__device__ float g_qkv[(size_t)BB*SS*3*DD];     // [B,S,3D]  48 MB
__device__ float g_att[(size_t)BB*SS*DD];       // [B,S,D]   16 MB
__device__ float g_wqkvT[(size_t)3*DD*DD];      // [3D, D]   12 MB
__device__ float g_wprojT[(size_t)DD*DD];       // [D, D]     4 MB

// ===========================================================================
// helpers
// ===========================================================================
__device__ __forceinline__ uint32_t f2tf32(float f) {
    uint32_t u;
    asm("cvt.rna.tf32.f32 %0, %1;" : "=r"(u) : "f"(f));
    return u;
}
__device__ __forceinline__ void mma_tf32(float* d, const uint32_t* a,
                                         const uint32_t* b) {
    asm volatile(
        "mma.sync.aligned.m16n8k8.row.col.f32.tf32.tf32.f32 "
        "{%0,%1,%2,%3}, {%4,%5,%6,%7}, {%8,%9}, {%0,%1,%2,%3};"
        : "+f"(d[0]), "+f"(d[1]), "+f"(d[2]), "+f"(d[3])
        : "r"(a[0]), "r"(a[1]), "r"(a[2]), "r"(a[3]), "r"(b[0]), "r"(b[1]));
}

// ===========================================================================
// Weight transpose: in[R,C] -> out[C,R]
// ===========================================================================
__global__ __launch_bounds__(256) void transpose_kernel(
    const float* __restrict__ in, float* __restrict__ out, int R, int C)
{
    __shared__ float t[32][33];
    int x0 = blockIdx.x * 32;
    int y0 = blockIdx.y * 32;
    int lx = threadIdx.x, ly = threadIdx.y;
    #pragma unroll
    for (int j = 0; j < 4; j++) {
        int r = ly + j * 8;
        t[r][lx] = in[(size_t)(y0 + r) * C + x0 + lx];
    }
    __syncthreads();
    #pragma unroll
    for (int j = 0; j < 4; j++) {
        int a = ly + j * 8;
        out[(size_t)(x0 + a) * R + y0 + lx] = t[lx][a];
    }
}

// ===========================================================================
// tf32 mma.sync GEMM: C[M,N] = A[M,K] @ Bt[N,K]^T + bias[N]
// CTA tile 128x128, K-chunk 32, 256 threads (8 warps, 4x2 grid of 32x64
// warp tiles). XOR-swizzled smem (16B granularity) for conflict-free access.
// ===========================================================================
#define BK 32
// word index within a tile for logical (row, word w in 0..31)
#define SWW(r, w) (((r) << 5) + (((((w) >> 2) ^ ((r) & 7))) << 2) + ((w) & 3))

__global__ __launch_bounds__(256) void gemm_mma_kernel(
    const float* __restrict__ A, const float* __restrict__ Bt,
    const float* __restrict__ bias, float* __restrict__ C,
    int M, int N, int K)
{
    __shared__ uint32_t As[128 * BK];
    __shared__ uint32_t Bs[128 * BK];
    __shared__ float    bias_s[128];

    int tid = threadIdx.x;
    int wid = tid >> 5;
    int lane = tid & 31;
    int wm = wid & 3;        // warp row (4 x 32 = 128 M)
    int wn = wid >> 2;       // warp col (2 x 64 = 128 N)
    int g = lane >> 2;       // 0..7
    int t = lane & 3;        // 0..3
    int m0 = blockIdx.y * 128;
    int n0 = blockIdx.x * 128;

    if (tid < 128) bias_s[tid] = bias[n0 + tid];

    float acc[2][8][4] = {};

    for (int k0 = 0; k0 < K; k0 += BK) {
        // load A and B tiles [128 x 32 f32], convert to tf32, swizzled store
        #pragma unroll
        for (int i = 0; i < 4; i++) {
            int fid = tid + i * 256;
            int row = fid >> 3;
            int c4  = fid & 7;
            int wbase = (row << 5) + ((c4 ^ (row & 7)) << 2);
            float4 a4 = *(const float4*)&A[(size_t)(m0 + row) * K + k0 + c4 * 4];
            uint4 ua;
            ua.x = f2tf32(a4.x); ua.y = f2tf32(a4.y);
            ua.z = f2tf32(a4.z); ua.w = f2tf32(a4.w);
            *(uint4*)&As[wbase] = ua;
            float4 b4 = *(const float4*)&Bt[(size_t)(n0 + row) * K + k0 + c4 * 4];
            uint4 ub;
            ub.x = f2tf32(b4.x); ub.y = f2tf32(b4.y);
            ub.z = f2tf32(b4.z); ub.w = f2tf32(b4.w);
            *(uint4*)&Bs[wbase] = ub;
        }
        __syncthreads();

        #pragma unroll
        for (int ks = 0; ks < 4; ks++) {
            uint32_t af[2][4];
            #pragma unroll
            for (int mt = 0; mt < 2; mt++) {
                int r0 = wm * 32 + mt * 16 + g;
                int r1 = r0 + 8;
                af[mt][0] = As[SWW(r0, 8 * ks + t)];
                af[mt][1] = As[SWW(r1, 8 * ks + t)];
                af[mt][2] = As[SWW(r0, 8 * ks + 4 + t)];
                af[mt][3] = As[SWW(r1, 8 * ks + 4 + t)];
            }
            uint32_t bf[8][2];
            #pragma unroll
            for (int nt = 0; nt < 8; nt++) {
                int n = wn * 64 + nt * 8 + g;
                bf[nt][0] = Bs[SWW(n, 8 * ks + t)];
                bf[nt][1] = Bs[SWW(n, 8 * ks + 4 + t)];
            }
            #pragma unroll
            for (int mt = 0; mt < 2; mt++)
                #pragma unroll
                for (int nt = 0; nt < 8; nt++)
                    mma_tf32(acc[mt][nt], af[mt], bf[nt]);
        }
        __syncthreads();
    }

    // epilogue: c0,c1 -> (row, 2t), (row, 2t+1); c2,c3 -> row+8
    #pragma unroll
    for (int mt = 0; mt < 2; mt++) {
        int r0 = m0 + wm * 32 + mt * 16 + g;
        #pragma unroll
        for (int nt = 0; nt < 8; nt++) {
            int cl = wn * 64 + nt * 8 + 2 * t;   // local col
            int cc = n0 + cl;
            float2 v0, v1;
            v0.x = acc[mt][nt][0] + bias_s[cl];
            v0.y = acc[mt][nt][1] + bias_s[cl + 1];
            v1.x = acc[mt][nt][2] + bias_s[cl];
            v1.y = acc[mt][nt][3] + bias_s[cl + 1];
            *(float2*)&C[(size_t)r0 * N + cc] = v0;
            *(float2*)&C[(size_t)(r0 + 8) * N + cc] = v1;
        }
    }
}

// ===========================================================================
// Flash-attention (fp32, causal) — unchanged (known-good)
// ===========================================================================
#define TQ 64
#define TK 64
#define AP 68

__global__ __launch_bounds__(256) void attn_kernel(
    const float* __restrict__ qkv, float* __restrict__ out)
{
    extern __shared__ float smf[];
    float* Qs  = smf;
    float* Ks  = Qs + TQ * AP;
    float* Vs  = Ks + TK * AP;
    float* Ss  = Vs + TK * AP;
    float* mrow = Ss + TQ * AP;
    float* lrow = mrow + TQ;
    float* arow = lrow + TQ;
    float* red  = arow + TQ;

    int qt = blockIdx.x;
    int h  = blockIdx.y;
    int b  = blockIdx.z;
    int tid = threadIdx.x;
    int ty = tid >> 4, tx = tid & 15;
    int qbase = qt * TQ;

    const size_t rstride = 3 * DD;
    const float* qptr0 = qkv + ((size_t)b * SS + qbase) * rstride + h * HD;

    for (int i = tid; i < TQ * HD; i += 256) {
        int r = i >> 6, d = i & 63;
        Qs[r * AP + d] = qptr0[(size_t)r * rstride + d];
    }
    if (tid < TQ) { mrow[tid] = -1e30f; lrow[tid] = 0.0f; }
    float O[4][4] = {};
    const float scale = 0.125f;
    __syncthreads();

    int row = tid & 63;
    int seg = tid >> 6;

    for (int kb = 0; kb <= qt; kb++) {
        int kbase = kb * TK;
        const float* kp = qkv + ((size_t)b * SS + kbase) * rstride + DD + h * HD;
        const float* vp = kp + DD;
        for (int i = tid; i < TK * HD; i += 256) {
            int r = i >> 6, d = i & 63;
            Ks[r * AP + d] = kp[(size_t)r * rstride + d];
            Vs[r * AP + d] = vp[(size_t)r * rstride + d];
        }
        __syncthreads();

        float acc[4][4] = {};
        #pragma unroll 8
        for (int d = 0; d < HD; d++) {
            float rq[4], rk[4];
            #pragma unroll
            for (int i = 0; i < 4; i++) rq[i] = Qs[(ty * 4 + i) * AP + d];
            #pragma unroll
            for (int j = 0; j < 4; j++) rk[j] = Ks[(tx * 4 + j) * AP + d];
            #pragma unroll
            for (int i = 0; i < 4; i++)
                #pragma unroll
                for (int j = 0; j < 4; j++)
                    acc[i][j] = fmaf(rq[i], rk[j], acc[i][j]);
        }
        bool diag = (kb == qt);
        #pragma unroll
        for (int i = 0; i < 4; i++) {
            #pragma unroll
            for (int j = 0; j < 4; j++) {
                float s = acc[i][j] * scale;
                if (diag && (tx * 4 + j) > (ty * 4 + i)) s = -1e30f;
                Ss[(ty * 4 + i) * AP + tx * 4 + j] = s;
            }
        }
        __syncthreads();

        float pm = -1e30f;
        #pragma unroll
        for (int c = 0; c < 16; c++)
            pm = fmaxf(pm, Ss[row * AP + seg * 16 + c]);
        red[seg * 64 + row] = pm;
        __syncthreads();
        if (seg == 0) {
            float mo = mrow[row];
            float mn = fmaxf(fmaxf(red[row], red[64 + row]),
                             fmaxf(red[128 + row], red[192 + row]));
            mn = fmaxf(mo, mn);
            float a = __expf(mo - mn);
            mrow[row] = mn;
            arow[row] = a;
            lrow[row] *= a;
        }
        __syncthreads();

        float mn = mrow[row];
        float ps = 0.0f;
        #pragma unroll
        for (int c = 0; c < 16; c++) {
            float p = __expf(Ss[row * AP + seg * 16 + c] - mn);
            Ss[row * AP + seg * 16 + c] = p;
            ps += p;
        }
        red[seg * 64 + row] = ps;
        __syncthreads();
        if (seg == 0)
            lrow[row] += red[row] + red[64 + row] + red[128 + row] + red[192 + row];

        float al[4];
        #pragma unroll
        for (int i = 0; i < 4; i++) al[i] = arow[ty * 4 + i];
        #pragma unroll
        for (int i = 0; i < 4; i++)
            #pragma unroll
            for (int j = 0; j < 4; j++)
                O[i][j] *= al[i];
        #pragma unroll 8
        for (int jk = 0; jk < TK; jk++) {
            float rp[4];
            #pragma unroll
            for (int i = 0; i < 4; i++) rp[i] = Ss[(ty * 4 + i) * AP + jk];
            float4 rv4 = *(const float4*)&Vs[jk * AP + tx * 4];
            float rv[4] = {rv4.x, rv4.y, rv4.z, rv4.w};
            #pragma unroll
            for (int i = 0; i < 4; i++)
                #pragma unroll
                for (int j = 0; j < 4; j++)
                    O[i][j] = fmaf(rp[i], rv[j], O[i][j]);
        }
        __syncthreads();
    }

    #pragma unroll
    for (int i = 0; i < 4; i++) {
        float inv = 1.0f / lrow[ty * 4 + i];
        float4 v;
        v.x = O[i][0] * inv;
        v.y = O[i][1] * inv;
        v.z = O[i][2] * inv;
        v.w = O[i][3] * inv;
        size_t orow = (size_t)b * SS + qbase + ty * 4 + i;
        *(float4*)&out[orow * DD + h * HD + tx * 4] = v;
    }
}

// ===========================================================================
// Launch
// ===========================================================================
extern "C" void kernel_launch(void* const* d_in, const int* in_sizes, int n_in,
                              void* d_out, int out_size)
{
    const float* x     = (const float*)d_in[0];
    const float* Wqkv  = (const float*)d_in[1];
    const float* bqkv  = (const float*)d_in[2];
    const float* Wproj = (const float*)d_in[3];
    const float* bproj = (const float*)d_in[4];
    float* out = (float*)d_out;

    float *qkv, *att, *wqkvT, *wprojT;
    cudaGetSymbolAddress((void**)&qkv, g_qkv);
    cudaGetSymbolAddress((void**)&att, g_att);
    cudaGetSymbolAddress((void**)&wqkvT, g_wqkvT);
    cudaGetSymbolAddress((void**)&wprojT, g_wprojT);

    // 0) transpose weights to [N, K] row-major
    transpose_kernel<<<dim3(3 * DD / 32, DD / 32), dim3(32, 8)>>>(
        Wqkv, wqkvT, DD, 3 * DD);
    transpose_kernel<<<dim3(DD / 32, DD / 32), dim3(32, 8)>>>(
        Wproj, wprojT, DD, DD);

    // 1) QKV projection: [4096,1024] @ [1024,3072] (tf32 mma.sync)
    gemm_mma_kernel<<<dim3(3 * DD / 128, MTOT / 128), 256>>>(
        x, wqkvT, bqkv, qkv, MTOT, 3 * DD, DD);

    // 2) causal flash attention (fp32)
    size_t smem_attn = (size_t)(4 * TQ * AP + 3 * TQ + 4 * TQ) * sizeof(float);
    cudaFuncSetAttribute(attn_kernel,
                         cudaFuncAttributeMaxDynamicSharedMemorySize,
                         (int)smem_attn);
    attn_kernel<<<dim3(SS / TQ, HH, BB), 256, smem_attn>>>(qkv, att);

    // 3) output projection: [4096,1024] @ [1024,1024] (tf32 mma.sync)
    gemm_mma_kernel<<<dim3(DD / 128, MTOT / 128), 256>>>(
        att, wprojT, bproj, out, MTOT, DD, DD);
}

// round 4
// speedup vs baseline: 3.6623x; 2.4688x over previous
#include <cuda_runtime.h>
#include <cuda_bf16.h>
#include <math.h>
#include <stdint.h>

// Problem constants
#define BB 2
#define SS 2048
#define DD 1024
#define HH 16
#define HD 64
#define MTOT (BB*SS)       // 4096

// Scratch (allocation-free rule: __device__ globals)
__device__ float g_qkv[(size_t)BB*SS*3*DD];     // [B,S,3D]  48 MB
__device__ float g_att[(size_t)BB*SS*DD];       // [B,S,D]   16 MB
__device__ float g_wqkvT[(size_t)3*DD*DD];      // [3D, D]   12 MB
__device__ float g_wprojT[(size_t)DD*DD];       // [D, D]     4 MB

// ===========================================================================
// helpers
// ===========================================================================
__device__ __forceinline__ uint32_t f2tf32(float f) {
    uint32_t u;
    asm("cvt.rna.tf32.f32 %0, %1;" : "=r"(u) : "f"(f));
    return u;
}
__device__ __forceinline__ void mma_tf32(float* d, const uint32_t* a,
                                         const uint32_t* b) {
    asm volatile(
        "mma.sync.aligned.m16n8k8.row.col.f32.tf32.tf32.f32 "
        "{%0,%1,%2,%3}, {%4,%5,%6,%7}, {%8,%9}, {%0,%1,%2,%3};"
        : "+f"(d[0]), "+f"(d[1]), "+f"(d[2]), "+f"(d[3])
        : "r"(a[0]), "r"(a[1]), "r"(a[2]), "r"(a[3]), "r"(b[0]), "r"(b[1]));
}

// ===========================================================================
// Weight transpose: in[R,C] -> out[C,R]
// ===========================================================================
__global__ __launch_bounds__(256) void transpose_kernel(
    const float* __restrict__ in, float* __restrict__ out, int R, int C)
{
    __shared__ float t[32][33];
    int x0 = blockIdx.x * 32;
    int y0 = blockIdx.y * 32;
    int lx = threadIdx.x, ly = threadIdx.y;
    #pragma unroll
    for (int j = 0; j < 4; j++) {
        int r = ly + j * 8;
        t[r][lx] = in[(size_t)(y0 + r) * C + x0 + lx];
    }
    __syncthreads();
    #pragma unroll
    for (int j = 0; j < 4; j++) {
        int a = ly + j * 8;
        out[(size_t)(x0 + a) * R + y0 + lx] = t[lx][a];
    }
}

// ===========================================================================
// tf32 mma.sync GEMM: C[M,N] = A[M,K] @ Bt[N,K]^T + bias[N]   (round-3 proven)
// ===========================================================================
#define BK 32
#define SWW(r, w) (((r) << 5) + (((((w) >> 2) ^ ((r) & 7))) << 2) + ((w) & 3))

__global__ __launch_bounds__(256) void gemm_mma_kernel(
    const float* __restrict__ A, const float* __restrict__ Bt,
    const float* __restrict__ bias, float* __restrict__ C,
    int M, int N, int K)
{
    __shared__ uint32_t As[128 * BK];
    __shared__ uint32_t Bs[128 * BK];
    __shared__ float    bias_s[128];

    int tid = threadIdx.x;
    int wid = tid >> 5;
    int lane = tid & 31;
    int wm = wid & 3;
    int wn = wid >> 2;
    int g = lane >> 2;
    int t = lane & 3;
    int m0 = blockIdx.y * 128;
    int n0 = blockIdx.x * 128;

    if (tid < 128) bias_s[tid] = bias[n0 + tid];

    float acc[2][8][4] = {};

    for (int k0 = 0; k0 < K; k0 += BK) {
        #pragma unroll
        for (int i = 0; i < 4; i++) {
            int fid = tid + i * 256;
            int row = fid >> 3;
            int c4  = fid & 7;
            int wbase = (row << 5) + ((c4 ^ (row & 7)) << 2);
            float4 a4 = *(const float4*)&A[(size_t)(m0 + row) * K + k0 + c4 * 4];
            uint4 ua;
            ua.x = f2tf32(a4.x); ua.y = f2tf32(a4.y);
            ua.z = f2tf32(a4.z); ua.w = f2tf32(a4.w);
            *(uint4*)&As[wbase] = ua;
            float4 b4 = *(const float4*)&Bt[(size_t)(n0 + row) * K + k0 + c4 * 4];
            uint4 ub;
            ub.x = f2tf32(b4.x); ub.y = f2tf32(b4.y);
            ub.z = f2tf32(b4.z); ub.w = f2tf32(b4.w);
            *(uint4*)&Bs[wbase] = ub;
        }
        __syncthreads();

        #pragma unroll
        for (int ks = 0; ks < 4; ks++) {
            uint32_t af[2][4];
            #pragma unroll
            for (int mt = 0; mt < 2; mt++) {
                int r0 = wm * 32 + mt * 16 + g;
                int r1 = r0 + 8;
                af[mt][0] = As[SWW(r0, 8 * ks + t)];
                af[mt][1] = As[SWW(r1, 8 * ks + t)];
                af[mt][2] = As[SWW(r0, 8 * ks + 4 + t)];
                af[mt][3] = As[SWW(r1, 8 * ks + 4 + t)];
            }
            uint32_t bf[8][2];
            #pragma unroll
            for (int nt = 0; nt < 8; nt++) {
                int n = wn * 64 + nt * 8 + g;
                bf[nt][0] = Bs[SWW(n, 8 * ks + t)];
                bf[nt][1] = Bs[SWW(n, 8 * ks + 4 + t)];
            }
            #pragma unroll
            for (int mt = 0; mt < 2; mt++)
                #pragma unroll
                for (int nt = 0; nt < 8; nt++)
                    mma_tf32(acc[mt][nt], af[mt], bf[nt]);
        }
        __syncthreads();
    }

    #pragma unroll
    for (int mt = 0; mt < 2; mt++) {
        int r0 = m0 + wm * 32 + mt * 16 + g;
        #pragma unroll
        for (int nt = 0; nt < 8; nt++) {
            int cl = wn * 64 + nt * 8 + 2 * t;
            int cc = n0 + cl;
            float2 v0, v1;
            v0.x = acc[mt][nt][0] + bias_s[cl];
            v0.y = acc[mt][nt][1] + bias_s[cl + 1];
            v1.x = acc[mt][nt][2] + bias_s[cl];
            v1.y = acc[mt][nt][3] + bias_s[cl + 1];
            *(float2*)&C[(size_t)r0 * N + cc] = v0;
            *(float2*)&C[(size_t)(r0 + 8) * N + cc] = v1;
        }
    }
}

// ===========================================================================
// Tensor-core flash attention (tf32 mma.sync, causal)
// CTA = 128 q-rows x (head, batch). 8 warps, warp w owns q-rows 16w..16w+15.
// K-block 64. Q frags preloaded to regs; Q smem reused as P buffer.
// smem strides 68 words -> frag access hits banks 4g+t (conflict-free).
// ===========================================================================
#define VP 68

__global__ __launch_bounds__(256) void attn_mma_kernel(
    const float* __restrict__ qkv, float* __restrict__ out)
{
    extern __shared__ uint32_t smu[];
    uint32_t* Qs = smu;              // 128*VP  (later: P buffer)
    uint32_t* Ks = Qs + 128 * VP;    // 64*VP
    uint32_t* Vt = Ks + 64 * VP;     // 64*VP   (transposed: [d][j])

    int tid = threadIdx.x;
    int w = tid >> 5, l = tid & 31;
    int g = l >> 2, t = l & 3;
    int qt = gridDim.x - 1 - blockIdx.x;   // heavy tiles first
    int qbase = qt * 128;
    int h = blockIdx.y, b = blockIdx.z;
    const size_t rs = 3 * DD;

    const float* qp = qkv + ((size_t)b * SS + qbase) * rs + h * HD;

    // cooperative load Q tile (scale folded), tf32
    #pragma unroll
    for (int i = 0; i < 8; i++) {
        int fid = tid + i * 256;
        int r = fid >> 4;
        int c = (fid & 15) << 2;
        float4 q4 = *(const float4*)&qp[(size_t)r * rs + c];
        uint32_t* d = &Qs[r * VP + c];
        d[0] = f2tf32(q4.x * 0.125f);
        d[1] = f2tf32(q4.y * 0.125f);
        d[2] = f2tf32(q4.z * 0.125f);
        d[3] = f2tf32(q4.w * 0.125f);
    }
    __syncthreads();

    // preload Q A-fragments (rows 16w+g, 16w+g+8)
    int rl0 = 16 * w + g;
    uint32_t aQ[8][4];
    #pragma unroll
    for (int kt = 0; kt < 8; kt++) {
        aQ[kt][0] = Qs[rl0 * VP + 8 * kt + t];
        aQ[kt][1] = Qs[(rl0 + 8) * VP + 8 * kt + t];
        aQ[kt][2] = Qs[rl0 * VP + 8 * kt + t + 4];
        aQ[kt][3] = Qs[(rl0 + 8) * VP + 8 * kt + t + 4];
    }

    float O[8][4] = {};
    float m0 = -1e30f, m1 = -1e30f, l0 = 0.0f, l1 = 0.0f;
    int row0 = qbase + rl0;
    int row1 = row0 + 8;
    int nkb = 2 * qt + 2;
    uint32_t* Pp = Qs;   // P overlays Q region (Q already in regs)

    for (int kb = 0; kb < nkb; kb++) {
        __syncthreads();   // prior iteration's smem reads complete
        const float* kp = qkv + ((size_t)b * SS + kb * 64) * rs + DD + h * HD;
        const float* vp = kp + DD;
        #pragma unroll
        for (int i = 0; i < 4; i++) {
            int fid = tid + i * 256;
            int r = fid >> 4;
            int c = (fid & 15) << 2;
            float4 k4 = *(const float4*)&kp[(size_t)r * rs + c];
            uint32_t* kd = &Ks[r * VP + c];
            kd[0] = f2tf32(k4.x); kd[1] = f2tf32(k4.y);
            kd[2] = f2tf32(k4.z); kd[3] = f2tf32(k4.w);
            float4 v4 = *(const float4*)&vp[(size_t)r * rs + c];
            Vt[(c + 0) * VP + r] = f2tf32(v4.x);
            Vt[(c + 1) * VP + r] = f2tf32(v4.y);
            Vt[(c + 2) * VP + r] = f2tf32(v4.z);
            Vt[(c + 3) * VP + r] = f2tf32(v4.w);
        }
        __syncthreads();

        // S = (Q*scale) @ K^T, 16x64 per warp
        float s[8][4] = {};
        #pragma unroll
        for (int kt = 0; kt < 8; kt++) {
            #pragma unroll
            for (int nt = 0; nt < 8; nt++) {
                uint32_t bf[2];
                bf[0] = Ks[(8 * nt + g) * VP + 8 * kt + t];
                bf[1] = Ks[(8 * nt + g) * VP + 8 * kt + t + 4];
                mma_tf32(s[nt], aQ[kt], bf);
            }
        }

        // causal mask
        if (kb * 64 + 63 > row0) {
            #pragma unroll
            for (int nt = 0; nt < 8; nt++) {
                int jg = kb * 64 + 8 * nt + 2 * t;
                if (jg     > row0) s[nt][0] = -1e30f;
                if (jg + 1 > row0) s[nt][1] = -1e30f;
                if (jg     > row1) s[nt][2] = -1e30f;
                if (jg + 1 > row1) s[nt][3] = -1e30f;
            }
        }

        // row max (lane-local + quad shuffle)
        float mx0 = -1e30f, mx1 = -1e30f;
        #pragma unroll
        for (int nt = 0; nt < 8; nt++) {
            mx0 = fmaxf(mx0, fmaxf(s[nt][0], s[nt][1]));
            mx1 = fmaxf(mx1, fmaxf(s[nt][2], s[nt][3]));
        }
        mx0 = fmaxf(mx0, __shfl_xor_sync(0xFFFFFFFF, mx0, 1));
        mx0 = fmaxf(mx0, __shfl_xor_sync(0xFFFFFFFF, mx0, 2));
        mx1 = fmaxf(mx1, __shfl_xor_sync(0xFFFFFFFF, mx1, 1));
        mx1 = fmaxf(mx1, __shfl_xor_sync(0xFFFFFFFF, mx1, 2));

        float mn0 = fmaxf(m0, mx0), mn1 = fmaxf(m1, mx1);
        float al0 = __expf(m0 - mn0), al1 = __expf(m1 - mn1);
        m0 = mn0; m1 = mn1;

        // P = exp(S - m): store tf32 to Pp, accumulate row sums
        float sum0 = 0.0f, sum1 = 0.0f;
        #pragma unroll
        for (int nt = 0; nt < 8; nt++) {
            float p0 = __expf(s[nt][0] - mn0);
            float p1 = __expf(s[nt][1] - mn0);
            float p2 = __expf(s[nt][2] - mn1);
            float p3 = __expf(s[nt][3] - mn1);
            sum0 += p0 + p1;
            sum1 += p2 + p3;
            uint2 u0; u0.x = f2tf32(p0); u0.y = f2tf32(p1);
            *(uint2*)&Pp[rl0 * VP + 8 * nt + 2 * t] = u0;
            uint2 u1; u1.x = f2tf32(p2); u1.y = f2tf32(p3);
            *(uint2*)&Pp[(rl0 + 8) * VP + 8 * nt + 2 * t] = u1;
        }
        sum0 += __shfl_xor_sync(0xFFFFFFFF, sum0, 1);
        sum0 += __shfl_xor_sync(0xFFFFFFFF, sum0, 2);
        sum1 += __shfl_xor_sync(0xFFFFFFFF, sum1, 1);
        sum1 += __shfl_xor_sync(0xFFFFFFFF, sum1, 2);
        l0 = l0 * al0 + sum0;
        l1 = l1 * al1 + sum1;

        // rescale O
        #pragma unroll
        for (int nt = 0; nt < 8; nt++) {
            O[nt][0] *= al0; O[nt][1] *= al0;
            O[nt][2] *= al1; O[nt][3] *= al1;
        }
        __syncwarp();   // P visible within warp (warp-private rows)

        // O += P @ V   (B operand = Vt[d][j])
        #pragma unroll
        for (int kt = 0; kt < 8; kt++) {
            uint32_t aP[4];
            aP[0] = Pp[rl0 * VP + 8 * kt + t];
            aP[1] = Pp[(rl0 + 8) * VP + 8 * kt + t];
            aP[2] = Pp[rl0 * VP + 8 * kt + t + 4];
            aP[3] = Pp[(rl0 + 8) * VP + 8 * kt + t + 4];
            #pragma unroll
            for (int nt = 0; nt < 8; nt++) {
                uint32_t bf[2];
                bf[0] = Vt[(8 * nt + g) * VP + 8 * kt + t];
                bf[1] = Vt[(8 * nt + g) * VP + 8 * kt + t + 4];
                mma_tf32(O[nt], aP, bf);
            }
        }
    }

    // finalize
    float i0 = 1.0f / l0, i1 = 1.0f / l1;
    float* op = out + (size_t)b * SS * DD + h * HD;
    #pragma unroll
    for (int nt = 0; nt < 8; nt++) {
        int c = 8 * nt + 2 * t;
        float2 o0; o0.x = O[nt][0] * i0; o0.y = O[nt][1] * i0;
        *(float2*)&op[(size_t)row0 * DD + c] = o0;
        float2 o1; o1.x = O[nt][2] * i1; o1.y = O[nt][3] * i1;
        *(float2*)&op[(size_t)row1 * DD + c] = o1;
    }
}

// ===========================================================================
// Launch
// ===========================================================================
extern "C" void kernel_launch(void* const* d_in, const int* in_sizes, int n_in,
                              void* d_out, int out_size)
{
    const float* x     = (const float*)d_in[0];
    const float* Wqkv  = (const float*)d_in[1];
    const float* bqkv  = (const float*)d_in[2];
    const float* Wproj = (const float*)d_in[3];
    const float* bproj = (const float*)d_in[4];
    float* out = (float*)d_out;

    float *qkv, *att, *wqkvT, *wprojT;
    cudaGetSymbolAddress((void**)&qkv, g_qkv);
    cudaGetSymbolAddress((void**)&att, g_att);
    cudaGetSymbolAddress((void**)&wqkvT, g_wqkvT);
    cudaGetSymbolAddress((void**)&wprojT, g_wprojT);

    // 0) transpose weights to [N, K] row-major
    transpose_kernel<<<dim3(3 * DD / 32, DD / 32), dim3(32, 8)>>>(
        Wqkv, wqkvT, DD, 3 * DD);
    transpose_kernel<<<dim3(DD / 32, DD / 32), dim3(32, 8)>>>(
        Wproj, wprojT, DD, DD);

    // 1) QKV projection (tf32 mma.sync)
    gemm_mma_kernel<<<dim3(3 * DD / 128, MTOT / 128), 256>>>(
        x, wqkvT, bqkv, qkv, MTOT, 3 * DD, DD);

    // 2) causal flash attention (tf32 mma.sync)
    size_t smem_attn = (size_t)(128 + 64 + 64) * VP * sizeof(uint32_t);
    cudaFuncSetAttribute(attn_mma_kernel,
                         cudaFuncAttributeMaxDynamicSharedMemorySize,
                         (int)smem_attn);
    attn_mma_kernel<<<dim3(SS / 128, HH, BB), 256, smem_attn>>>(qkv, att);

    // 3) output projection (tf32 mma.sync)
    gemm_mma_kernel<<<dim3(DD / 128, MTOT / 128), 256>>>(
        att, wprojT, bproj, out, MTOT, DD, DD);
}

// round 5
// speedup vs baseline: 3.8414x; 1.0489x over previous
#include <cuda_runtime.h>
#include <cuda_bf16.h>
#include <math.h>
#include <stdint.h>

// Problem constants
#define BB 2
#define SS 2048
#define DD 1024
#define HH 16
#define HD 64
#define MTOT (BB*SS)       // 4096

// Scratch (allocation-free rule: __device__ globals)
__device__ float g_qkv[(size_t)BB*SS*3*DD];     // [B,S,3D] tf32-rounded
__device__ float g_att[(size_t)BB*SS*DD];       // [B,S,D]  tf32-rounded
__device__ float g_wqkvT[(size_t)3*DD*DD];      // [3D, D]  tf32-rounded
__device__ float g_wprojT[(size_t)DD*DD];       // [D, D]   tf32-rounded
__device__ float g_xcvt[(size_t)MTOT*DD];       // [B,S,D]  tf32-rounded

// ===========================================================================
// helpers
// ===========================================================================
__device__ __forceinline__ uint32_t f2tf32(float f) {
    uint32_t u;
    asm("cvt.rna.tf32.f32 %0, %1;" : "=r"(u) : "f"(f));
    return u;
}
__device__ __forceinline__ void mma_tf32(float* d, const uint32_t* a,
                                         const uint32_t* b) {
    asm volatile(
        "mma.sync.aligned.m16n8k8.row.col.f32.tf32.tf32.f32 "
        "{%0,%1,%2,%3}, {%4,%5,%6,%7}, {%8,%9}, {%0,%1,%2,%3};"
        : "+f"(d[0]), "+f"(d[1]), "+f"(d[2]), "+f"(d[3])
        : "r"(a[0]), "r"(a[1]), "r"(a[2]), "r"(a[3]), "r"(b[0]), "r"(b[1]));
}
__device__ __forceinline__ uint32_t smem_u32(const void* p) {
    uint32_t a;
    asm("{ .reg .u64 t; cvta.to.shared.u64 t, %1; cvt.u32.u64 %0, t; }"
        : "=r"(a) : "l"(p));
    return a;
}
__device__ __forceinline__ void cp_async16(uint32_t dst, const void* src) {
    asm volatile("cp.async.cg.shared.global [%0], [%1], 16;"
                 :: "r"(dst), "l"(src));
}
__device__ __forceinline__ void cp_commit() {
    asm volatile("cp.async.commit_group;" ::: "memory");
}
template<int N> __device__ __forceinline__ void cp_wait() {
    asm volatile("cp.async.wait_group %0;" :: "n"(N) : "memory");
}

// ===========================================================================
// x -> tf32-rounded copy
// ===========================================================================
__global__ __launch_bounds__(256) void cvt_tf32_kernel(
    const float* __restrict__ in, float* __restrict__ out)
{
    size_t i = ((size_t)blockIdx.x * 256 + threadIdx.x) * 4;
    float4 v = *(const float4*)&in[i];
    uint4 u;
    u.x = f2tf32(v.x); u.y = f2tf32(v.y);
    u.z = f2tf32(v.z); u.w = f2tf32(v.w);
    *(uint4*)&out[i] = u;
}

// ===========================================================================
// Weight transpose + tf32 round: in[R,C] -> out[C,R]
// ===========================================================================
__global__ __launch_bounds__(256) void transpose_kernel(
    const float* __restrict__ in, float* __restrict__ out, int R, int C)
{
    __shared__ float t[32][33];
    int x0 = blockIdx.x * 32;
    int y0 = blockIdx.y * 32;
    int lx = threadIdx.x, ly = threadIdx.y;
    #pragma unroll
    for (int j = 0; j < 4; j++) {
        int r = ly + j * 8;
        t[r][lx] = in[(size_t)(y0 + r) * C + x0 + lx];
    }
    __syncthreads();
    #pragma unroll
    for (int j = 0; j < 4; j++) {
        int a = ly + j * 8;
        out[(size_t)(x0 + a) * R + y0 + lx] =
            __uint_as_float(f2tf32(t[lx][a]));
    }
}

// ===========================================================================
// tf32 mma.sync GEMM, cp.async 3-stage pipeline.
// C[M,N] = A[M,K] @ Bt[N,K]^T + bias[N].  A/Bt are PRE-ROUNDED tf32 bits.
// CTA tile 128x128, K-chunk 32, 256 threads (8 warps 4x2, 32x64 warp tiles).
// cvt_out: 1 -> round outputs to tf32 (feeds another mma stage), 0 -> fp32.
// ===========================================================================
#define BK 32
#define NSTG 3
#define SWW(r, w) (((r) << 5) + (((((w) >> 2) ^ ((r) & 7))) << 2) + ((w) & 3))

__global__ __launch_bounds__(256) void gemm_mma_kernel(
    const float* __restrict__ A, const float* __restrict__ Bt,
    const float* __restrict__ bias, float* __restrict__ C,
    int M, int N, int K, int cvt_out)
{
    __shared__ uint32_t As[NSTG][128 * BK];
    __shared__ uint32_t Bs[NSTG][128 * BK];
    __shared__ float    bias_s[128];

    int tid = threadIdx.x;
    int wid = tid >> 5;
    int lane = tid & 31;
    int wm = wid & 3;
    int wn = wid >> 2;
    int g = lane >> 2;
    int t = lane & 3;
    int m0 = blockIdx.y * 128;
    int n0 = blockIdx.x * 128;
    int nchunk = K / BK;

    if (tid < 128) bias_s[tid] = bias[n0 + tid];

    // per-thread load geometry: 4 x 16B per matrix per chunk
    int lrow[4], lwoff[4];
    #pragma unroll
    for (int i = 0; i < 4; i++) {
        int u = tid + i * 256;
        int row = u >> 3;
        int c4  = u & 7;
        lrow[i] = row;
        lwoff[i] = (row << 5) + ((c4 ^ (row & 7)) << 2);
    }
    int lc4[4];
    #pragma unroll
    for (int i = 0; i < 4; i++) lc4[i] = ((tid + i * 256) & 7) * 4;

    uint32_t sA = smem_u32(&As[0][0]);
    uint32_t sB = smem_u32(&Bs[0][0]);
    const uint32_t stg_bytes = 128 * BK * 4;

    // prologue: issue chunks 0, 1
    #pragma unroll
    for (int s = 0; s < NSTG - 1; s++) {
        int k0 = s * BK;
        #pragma unroll
        for (int i = 0; i < 4; i++) {
            cp_async16(sA + s * stg_bytes + lwoff[i] * 4,
                       &A[(size_t)(m0 + lrow[i]) * K + k0 + lc4[i]]);
            cp_async16(sB + s * stg_bytes + lwoff[i] * 4,
                       &Bt[(size_t)(n0 + lrow[i]) * K + k0 + lc4[i]]);
        }
        cp_commit();
    }

    float acc[2][8][4] = {};

    for (int c = 0; c < nchunk; c++) {
        cp_wait<NSTG - 2>();
        __syncthreads();

        int cn = c + NSTG - 1;
        if (cn < nchunk) {
            int st = cn % NSTG;
            int k0 = cn * BK;
            #pragma unroll
            for (int i = 0; i < 4; i++) {
                cp_async16(sA + st * stg_bytes + lwoff[i] * 4,
                           &A[(size_t)(m0 + lrow[i]) * K + k0 + lc4[i]]);
                cp_async16(sB + st * stg_bytes + lwoff[i] * 4,
                           &Bt[(size_t)(n0 + lrow[i]) * K + k0 + lc4[i]]);
            }
        }
        cp_commit();

        const uint32_t* Ac = As[c % NSTG];
        const uint32_t* Bc = Bs[c % NSTG];
        #pragma unroll
        for (int ks = 0; ks < 4; ks++) {
            uint32_t af[2][4];
            #pragma unroll
            for (int mt = 0; mt < 2; mt++) {
                int r0 = wm * 32 + mt * 16 + g;
                int r1 = r0 + 8;
                af[mt][0] = Ac[SWW(r0, 8 * ks + t)];
                af[mt][1] = Ac[SWW(r1, 8 * ks + t)];
                af[mt][2] = Ac[SWW(r0, 8 * ks + 4 + t)];
                af[mt][3] = Ac[SWW(r1, 8 * ks + 4 + t)];
            }
            uint32_t bf[8][2];
            #pragma unroll
            for (int nt = 0; nt < 8; nt++) {
                int n = wn * 64 + nt * 8 + g;
                bf[nt][0] = Bc[SWW(n, 8 * ks + t)];
                bf[nt][1] = Bc[SWW(n, 8 * ks + 4 + t)];
            }
            #pragma unroll
            for (int mt = 0; mt < 2; mt++)
                #pragma unroll
                for (int nt = 0; nt < 8; nt++)
                    mma_tf32(acc[mt][nt], af[mt], bf[nt]);
        }
    }

    #pragma unroll
    for (int mt = 0; mt < 2; mt++) {
        int r0 = m0 + wm * 32 + mt * 16 + g;
        #pragma unroll
        for (int nt = 0; nt < 8; nt++) {
            int cl = wn * 64 + nt * 8 + 2 * t;
            int cc = n0 + cl;
            float v00 = acc[mt][nt][0] + bias_s[cl];
            float v01 = acc[mt][nt][1] + bias_s[cl + 1];
            float v10 = acc[mt][nt][2] + bias_s[cl];
            float v11 = acc[mt][nt][3] + bias_s[cl + 1];
            float2 v0, v1;
            if (cvt_out) {
                v0.x = __uint_as_float(f2tf32(v00));
                v0.y = __uint_as_float(f2tf32(v01));
                v1.x = __uint_as_float(f2tf32(v10));
                v1.y = __uint_as_float(f2tf32(v11));
            } else {
                v0.x = v00; v0.y = v01; v1.x = v10; v1.y = v11;
            }
            *(float2*)&C[(size_t)r0 * N + cc] = v0;
            *(float2*)&C[(size_t)(r0 + 8) * N + cc] = v1;
        }
    }
}

// ===========================================================================
// Tensor-core flash attention (tf32 mma.sync, causal). qkv is tf32-rounded.
// CTA = 128 q-rows x (head, batch). 8 warps, warp w owns q-rows 16w..16w+15.
// Output written tf32-rounded (feeds proj GEMM).
// ===========================================================================
#define VP 68

__global__ __launch_bounds__(256) void attn_mma_kernel(
    const float* __restrict__ qkv, float* __restrict__ out)
{
    extern __shared__ uint32_t smu[];
    uint32_t* Qs = smu;              // 128*VP  (later: P buffer)
    uint32_t* Ks = Qs + 128 * VP;    // 64*VP
    uint32_t* Vt = Ks + 64 * VP;     // 64*VP   (transposed: [d][j])

    int tid = threadIdx.x;
    int w = tid >> 5, l = tid & 31;
    int g = l >> 2, t = l & 3;
    int qt = gridDim.x - 1 - blockIdx.x;   // heavy tiles first
    int qbase = qt * 128;
    int h = blockIdx.y, b = blockIdx.z;
    const size_t rs = 3 * DD;

    const float* qp = qkv + ((size_t)b * SS + qbase) * rs + h * HD;

    // cooperative load Q tile; *0.125 is exact (pow2), stays tf32-clean
    #pragma unroll
    for (int i = 0; i < 8; i++) {
        int fid = tid + i * 256;
        int r = fid >> 4;
        int c = (fid & 15) << 2;
        float4 q4 = *(const float4*)&qp[(size_t)r * rs + c];
        uint32_t* d = &Qs[r * VP + c];
        d[0] = __float_as_uint(q4.x * 0.125f);
        d[1] = __float_as_uint(q4.y * 0.125f);
        d[2] = __float_as_uint(q4.z * 0.125f);
        d[3] = __float_as_uint(q4.w * 0.125f);
    }
    __syncthreads();

    // preload Q A-fragments (rows 16w+g, 16w+g+8)
    int rl0 = 16 * w + g;
    uint32_t aQ[8][4];
    #pragma unroll
    for (int kt = 0; kt < 8; kt++) {
        aQ[kt][0] = Qs[rl0 * VP + 8 * kt + t];
        aQ[kt][1] = Qs[(rl0 + 8) * VP + 8 * kt + t];
        aQ[kt][2] = Qs[rl0 * VP + 8 * kt + t + 4];
        aQ[kt][3] = Qs[(rl0 + 8) * VP + 8 * kt + t + 4];
    }

    float O[8][4] = {};
    float m0 = -1e30f, m1 = -1e30f, l0 = 0.0f, l1 = 0.0f;
    int row0 = qbase + rl0;
    int row1 = row0 + 8;
    int nkb = 2 * qt + 2;
    uint32_t* Pp = Qs;   // P overlays Q region (Q already in regs)

    for (int kb = 0; kb < nkb; kb++) {
        __syncthreads();
        const float* kp = qkv + ((size_t)b * SS + kb * 64) * rs + DD + h * HD;
        const float* vp = kp + DD;
        #pragma unroll
        for (int i = 0; i < 4; i++) {
            int fid = tid + i * 256;
            int r = fid >> 4;
            int c = (fid & 15) << 2;
            uint4 k4 = *(const uint4*)&kp[(size_t)r * rs + c];
            *(uint4*)&Ks[r * VP + c] = k4;
            uint4 v4 = *(const uint4*)&vp[(size_t)r * rs + c];
            Vt[(c + 0) * VP + r] = v4.x;
            Vt[(c + 1) * VP + r] = v4.y;
            Vt[(c + 2) * VP + r] = v4.z;
            Vt[(c + 3) * VP + r] = v4.w;
        }
        __syncthreads();

        // S = (Q*scale) @ K^T, 16x64 per warp
        float s[8][4] = {};
        #pragma unroll
        for (int kt = 0; kt < 8; kt++) {
            #pragma unroll
            for (int nt = 0; nt < 8; nt++) {
                uint32_t bf[2];
                bf[0] = Ks[(8 * nt + g) * VP + 8 * kt + t];
                bf[1] = Ks[(8 * nt + g) * VP + 8 * kt + t + 4];
                mma_tf32(s[nt], aQ[kt], bf);
            }
        }

        // causal mask
        if (kb * 64 + 63 > row0) {
            #pragma unroll
            for (int nt = 0; nt < 8; nt++) {
                int jg = kb * 64 + 8 * nt + 2 * t;
                if (jg     > row0) s[nt][0] = -1e30f;
                if (jg + 1 > row0) s[nt][1] = -1e30f;
                if (jg     > row1) s[nt][2] = -1e30f;
                if (jg + 1 > row1) s[nt][3] = -1e30f;
            }
        }

        // row max
        float mx0 = -1e30f, mx1 = -1e30f;
        #pragma unroll
        for (int nt = 0; nt < 8; nt++) {
            mx0 = fmaxf(mx0, fmaxf(s[nt][0], s[nt][1]));
            mx1 = fmaxf(mx1, fmaxf(s[nt][2], s[nt][3]));
        }
        mx0 = fmaxf(mx0, __shfl_xor_sync(0xFFFFFFFF, mx0, 1));
        mx0 = fmaxf(mx0, __shfl_xor_sync(0xFFFFFFFF, mx0, 2));
        mx1 = fmaxf(mx1, __shfl_xor_sync(0xFFFFFFFF, mx1, 1));
        mx1 = fmaxf(mx1, __shfl_xor_sync(0xFFFFFFFF, mx1, 2));

        float mn0 = fmaxf(m0, mx0), mn1 = fmaxf(m1, mx1);
        float al0 = __expf(m0 - mn0), al1 = __expf(m1 - mn1);
        m0 = mn0; m1 = mn1;

        // P = exp(S - m): store tf32 to Pp, accumulate row sums
        float sum0 = 0.0f, sum1 = 0.0f;
        #pragma unroll
        for (int nt = 0; nt < 8; nt++) {
            float p0 = __expf(s[nt][0] - mn0);
            float p1 = __expf(s[nt][1] - mn0);
            float p2 = __expf(s[nt][2] - mn1);
            float p3 = __expf(s[nt][3] - mn1);
            sum0 += p0 + p1;
            sum1 += p2 + p3;
            uint2 u0; u0.x = f2tf32(p0); u0.y = f2tf32(p1);
            *(uint2*)&Pp[rl0 * VP + 8 * nt + 2 * t] = u0;
            uint2 u1; u1.x = f2tf32(p2); u1.y = f2tf32(p3);
            *(uint2*)&Pp[(rl0 + 8) * VP + 8 * nt + 2 * t] = u1;
        }
        sum0 += __shfl_xor_sync(0xFFFFFFFF, sum0, 1);
        sum0 += __shfl_xor_sync(0xFFFFFFFF, sum0, 2);
        sum1 += __shfl_xor_sync(0xFFFFFFFF, sum1, 1);
        sum1 += __shfl_xor_sync(0xFFFFFFFF, sum1, 2);
        l0 = l0 * al0 + sum0;
        l1 = l1 * al1 + sum1;

        // rescale O
        #pragma unroll
        for (int nt = 0; nt < 8; nt++) {
            O[nt][0] *= al0; O[nt][1] *= al0;
            O[nt][2] *= al1; O[nt][3] *= al1;
        }
        __syncwarp();   // P visible within warp (warp-private rows)

        // O += P @ V
        #pragma unroll
        for (int kt = 0; kt < 8; kt++) {
            uint32_t aP[4];
            aP[0] = Pp[rl0 * VP + 8 * kt + t];
            aP[1] = Pp[(rl0 + 8) * VP + 8 * kt + t];
            aP[2] = Pp[rl0 * VP + 8 * kt + t + 4];
            aP[3] = Pp[(rl0 + 8) * VP + 8 * kt + t + 4];
            #pragma unroll
            for (int nt = 0; nt < 8; nt++) {
                uint32_t bf[2];
                bf[0] = Vt[(8 * nt + g) * VP + 8 * kt + t];
                bf[1] = Vt[(8 * nt + g) * VP + 8 * kt + t + 4];
                mma_tf32(O[nt], aP, bf);
            }
        }
    }

    // finalize; write tf32-rounded (consumed by proj GEMM)
    float i0 = 1.0f / l0, i1 = 1.0f / l1;
    float* op = out + (size_t)b * SS * DD + h * HD;
    #pragma unroll
    for (int nt = 0; nt < 8; nt++) {
        int c = 8 * nt + 2 * t;
        float2 o0;
        o0.x = __uint_as_float(f2tf32(O[nt][0] * i0));
        o0.y = __uint_as_float(f2tf32(O[nt][1] * i0));
        *(float2*)&op[(size_t)row0 * DD + c] = o0;
        float2 o1;
        o1.x = __uint_as_float(f2tf32(O[nt][2] * i1));
        o1.y = __uint_as_float(f2tf32(O[nt][3] * i1));
        *(float2*)&op[(size_t)row1 * DD + c] = o1;
    }
}

// ===========================================================================
// Launch
// ===========================================================================
extern "C" void kernel_launch(void* const* d_in, const int* in_sizes, int n_in,
                              void* d_out, int out_size)
{
    const float* x     = (const float*)d_in[0];
    const float* Wqkv  = (const float*)d_in[1];
    const float* bqkv  = (const float*)d_in[2];
    const float* Wproj = (const float*)d_in[3];
    const float* bproj = (const float*)d_in[4];
    float* out = (float*)d_out;

    float *qkv, *att, *wqkvT, *wprojT, *xcvt;
    cudaGetSymbolAddress((void**)&qkv, g_qkv);
    cudaGetSymbolAddress((void**)&att, g_att);
    cudaGetSymbolAddress((void**)&wqkvT, g_wqkvT);
    cudaGetSymbolAddress((void**)&wprojT, g_wprojT);
    cudaGetSymbolAddress((void**)&xcvt, g_xcvt);

    // 0) pre-round operands to tf32
    cvt_tf32_kernel<<<(MTOT * DD) / (256 * 4), 256>>>(x, xcvt);
    transpose_kernel<<<dim3(3 * DD / 32, DD / 32), dim3(32, 8)>>>(
        Wqkv, wqkvT, DD, 3 * DD);
    transpose_kernel<<<dim3(DD / 32, DD / 32), dim3(32, 8)>>>(
        Wproj, wprojT, DD, DD);

    // 1) QKV projection (pipelined tf32 mma.sync), output tf32-rounded
    gemm_mma_kernel<<<dim3(3 * DD / 128, MTOT / 128), 256>>>(
        xcvt, wqkvT, bqkv, qkv, MTOT, 3 * DD, DD, 1);

    // 2) causal flash attention (tf32 mma.sync), output tf32-rounded
    size_t smem_attn = (size_t)(128 + 64 + 64) * VP * sizeof(uint32_t);
    cudaFuncSetAttribute(attn_mma_kernel,
                         cudaFuncAttributeMaxDynamicSharedMemorySize,
                         (int)smem_attn);
    attn_mma_kernel<<<dim3(SS / 128, HH, BB), 256, smem_attn>>>(qkv, att);

    // 3) output projection (pipelined tf32 mma.sync), fp32 output
    gemm_mma_kernel<<<dim3(DD / 128, MTOT / 128), 256>>>(
        att, wprojT, bproj, out, MTOT, DD, DD, 0);
}

// round 7
// speedup vs baseline: 4.5770x; 1.1915x over previous
#include <cuda_runtime.h>
#include <cuda_bf16.h>
#include <math.h>
#include <stdint.h>

// Problem constants
#define BB 2
#define SS 2048
#define DD 1024
#define HH 16
#define HD 64
#define MTOT (BB*SS)       // 4096

// Scratch (allocation-free rule: __device__ globals)
__device__ float g_qkv[(size_t)BB*SS*3*DD];     // [B,S,3D] tf32-rounded
__device__ float g_att[(size_t)BB*SS*DD];       // [B,S,D]  tf32-rounded
__device__ float g_wqkvT[(size_t)3*DD*DD];      // [3D, D]  tf32-rounded
__device__ float g_wprojT[(size_t)DD*DD];       // [D, D]   tf32-rounded
__device__ float g_xcvt[(size_t)MTOT*DD];       // [B,S,D]  tf32-rounded

// ===========================================================================
// helpers
// ===========================================================================
__device__ __forceinline__ uint32_t f2tf32(float f) {
    uint32_t u;
    asm("cvt.rna.tf32.f32 %0, %1;" : "=r"(u) : "f"(f));
    return u;
}
__device__ __forceinline__ float ex2f(float x) {
    float r;
    asm("ex2.approx.ftz.f32 %0, %1;" : "=f"(r) : "f"(x));
    return r;
}
__device__ __forceinline__ void mma_tf32(float* d, const uint32_t* a,
                                         const uint32_t* b) {
    asm volatile(
        "mma.sync.aligned.m16n8k8.row.col.f32.tf32.tf32.f32 "
        "{%0,%1,%2,%3}, {%4,%5,%6,%7}, {%8,%9}, {%0,%1,%2,%3};"
        : "+f"(d[0]), "+f"(d[1]), "+f"(d[2]), "+f"(d[3])
        : "r"(a[0]), "r"(a[1]), "r"(a[2]), "r"(a[3]), "r"(b[0]), "r"(b[1]));
}
__device__ __forceinline__ uint32_t smem_u32(const void* p) {
    uint32_t a;
    asm("{ .reg .u64 t; cvta.to.shared.u64 t, %1; cvt.u32.u64 %0, t; }"
        : "=r"(a) : "l"(p));
    return a;
}
__device__ __forceinline__ void cp_async16(uint32_t dst, const void* src) {
    asm volatile("cp.async.cg.shared.global [%0], [%1], 16;"
                 :: "r"(dst), "l"(src));
}
__device__ __forceinline__ void cp_commit() {
    asm volatile("cp.async.commit_group;" ::: "memory");
}
template<int N> __device__ __forceinline__ void cp_wait() {
    asm volatile("cp.async.wait_group %0;" :: "n"(N) : "memory");
}

// ===========================================================================
// x -> tf32-rounded copy
// ===========================================================================
__global__ __launch_bounds__(256) void cvt_tf32_kernel(
    const float* __restrict__ in, float* __restrict__ out)
{
    size_t i = ((size_t)blockIdx.x * 256 + threadIdx.x) * 4;
    float4 v = *(const float4*)&in[i];
    uint4 u;
    u.x = f2tf32(v.x); u.y = f2tf32(v.y);
    u.z = f2tf32(v.z); u.w = f2tf32(v.w);
    *(uint4*)&out[i] = u;
}

// ===========================================================================
// Weight transpose + tf32 round: in[R,C] -> out[C,R]
// ===========================================================================
__global__ __launch_bounds__(256) void transpose_kernel(
    const float* __restrict__ in, float* __restrict__ out, int R, int C)
{
    __shared__ float t[32][33];
    int x0 = blockIdx.x * 32;
    int y0 = blockIdx.y * 32;
    int lx = threadIdx.x, ly = threadIdx.y;
    #pragma unroll
    for (int j = 0; j < 4; j++) {
        int r = ly + j * 8;
        t[r][lx] = in[(size_t)(y0 + r) * C + x0 + lx];
    }
    __syncthreads();
    #pragma unroll
    for (int j = 0; j < 4; j++) {
        int a = ly + j * 8;
        out[(size_t)(x0 + a) * R + y0 + lx] =
            __uint_as_float(f2tf32(t[lx][a]));
    }
}

// ===========================================================================
// tf32 mma.sync GEMM, cp.async 3-stage pipeline, 2 CTAs/SM.
// C[M,N] = A[M,K] @ Bt[N,K]^T + bias[N].  A/Bt are PRE-ROUNDED tf32 bits.
// ===========================================================================
#define BK 32
#define NSTG 3
#define SWW(r, w) (((r) << 5) + (((((w) >> 2) ^ ((r) & 7))) << 2) + ((w) & 3))

__global__ __launch_bounds__(256, 2) void gemm_mma_kernel(
    const float* __restrict__ A, const float* __restrict__ Bt,
    const float* __restrict__ bias, float* __restrict__ C,
    int M, int N, int K, int cvt_out)
{
    __shared__ uint32_t As[NSTG][128 * BK];
    __shared__ uint32_t Bs[NSTG][128 * BK];
    __shared__ float    bias_s[128];

    int tid = threadIdx.x;
    int wid = tid >> 5;
    int lane = tid & 31;
    int wm = wid & 3;
    int wn = wid >> 2;
    int g = lane >> 2;
    int t = lane & 3;
    int m0 = blockIdx.y * 128;
    int n0 = blockIdx.x * 128;
    int nchunk = K / BK;

    if (tid < 128) bias_s[tid] = bias[n0 + tid];

    // per-thread load geometry: 4 x 16B per matrix per chunk
    int lrow[4], lwoff[4], lc4[4];
    #pragma unroll
    for (int i = 0; i < 4; i++) {
        int u = tid + i * 256;
        int row = u >> 3;
        int c4  = u & 7;
        lrow[i] = row;
        lwoff[i] = (row << 5) + ((c4 ^ (row & 7)) << 2);
        lc4[i] = c4 * 4;
    }

    uint32_t sA = smem_u32(&As[0][0]);
    uint32_t sB = smem_u32(&Bs[0][0]);
    const uint32_t stg_bytes = 128 * BK * 4;

    #pragma unroll
    for (int s = 0; s < NSTG - 1; s++) {
        int k0 = s * BK;
        #pragma unroll
        for (int i = 0; i < 4; i++) {
            cp_async16(sA + s * stg_bytes + lwoff[i] * 4,
                       &A[(size_t)(m0 + lrow[i]) * K + k0 + lc4[i]]);
            cp_async16(sB + s * stg_bytes + lwoff[i] * 4,
                       &Bt[(size_t)(n0 + lrow[i]) * K + k0 + lc4[i]]);
        }
        cp_commit();
    }

    float acc[2][8][4] = {};

    for (int c = 0; c < nchunk; c++) {
        cp_wait<NSTG - 2>();
        __syncthreads();

        int cn = c + NSTG - 1;
        if (cn < nchunk) {
            int st = cn % NSTG;
            int k0 = cn * BK;
            #pragma unroll
            for (int i = 0; i < 4; i++) {
                cp_async16(sA + st * stg_bytes + lwoff[i] * 4,
                           &A[(size_t)(m0 + lrow[i]) * K + k0 + lc4[i]]);
                cp_async16(sB + st * stg_bytes + lwoff[i] * 4,
                           &Bt[(size_t)(n0 + lrow[i]) * K + k0 + lc4[i]]);
            }
        }
        cp_commit();

        const uint32_t* Ac = As[c % NSTG];
        const uint32_t* Bc = Bs[c % NSTG];
        #pragma unroll
        for (int ks = 0; ks < 4; ks++) {
            uint32_t af[2][4];
            #pragma unroll
            for (int mt = 0; mt < 2; mt++) {
                int r0 = wm * 32 + mt * 16 + g;
                int r1 = r0 + 8;
                af[mt][0] = Ac[SWW(r0, 8 * ks + t)];
                af[mt][1] = Ac[SWW(r1, 8 * ks + t)];
                af[mt][2] = Ac[SWW(r0, 8 * ks + 4 + t)];
                af[mt][3] = Ac[SWW(r1, 8 * ks + 4 + t)];
            }
            uint32_t bf[8][2];
            #pragma unroll
            for (int nt = 0; nt < 8; nt++) {
                int n = wn * 64 + nt * 8 + g;
                bf[nt][0] = Bc[SWW(n, 8 * ks + t)];
                bf[nt][1] = Bc[SWW(n, 8 * ks + 4 + t)];
            }
            #pragma unroll
            for (int mt = 0; mt < 2; mt++)
                #pragma unroll
                for (int nt = 0; nt < 8; nt++)
                    mma_tf32(acc[mt][nt], af[mt], bf[nt]);
        }
    }

    #pragma unroll
    for (int mt = 0; mt < 2; mt++) {
        int r0 = m0 + wm * 32 + mt * 16 + g;
        #pragma unroll
        for (int nt = 0; nt < 8; nt++) {
            int cl = wn * 64 + nt * 8 + 2 * t;
            int cc = n0 + cl;
            float v00 = acc[mt][nt][0] + bias_s[cl];
            float v01 = acc[mt][nt][1] + bias_s[cl + 1];
            float v10 = acc[mt][nt][2] + bias_s[cl];
            float v11 = acc[mt][nt][3] + bias_s[cl + 1];
            float2 v0, v1;
            if (cvt_out) {
                v0.x = __uint_as_float(f2tf32(v00));
                v0.y = __uint_as_float(f2tf32(v01));
                v1.x = __uint_as_float(f2tf32(v10));
                v1.y = __uint_as_float(f2tf32(v11));
            } else {
                v0.x = v00; v0.y = v01; v1.x = v10; v1.y = v11;
            }
            *(float2*)&C[(size_t)r0 * N + cc] = v0;
            *(float2*)&C[(size_t)(r0 + 8) * N + cc] = v1;
        }
    }
}

// ===========================================================================
// Tensor-core flash attention (tf32 mma.sync, causal), cp.async K/V pipeline.
// CTA = 128 q-rows x (head, batch). 8 warps, warp w owns q-rows 16w..16w+15.
// Softmax in exp2 domain (log2e folded into Q scale).
// K row-layout stride 68 (frag banks 4g+t), V row-layout stride 72 (8t+g).
// ===========================================================================
#define VP  68
#define VPV 72

__global__ __launch_bounds__(256, 2) void attn_mma_kernel(
    const float* __restrict__ qkv, float* __restrict__ out)
{
    extern __shared__ uint32_t smu[];
    uint32_t* Qs = smu;                       // 128*VP (later: P buffer)
    uint32_t* Kb = Qs + 128 * VP;             // 2 x 64*VP
    uint32_t* Vb = Kb + 2 * 64 * VP;          // 2 x 64*VPV

    int tid = threadIdx.x;
    int w = tid >> 5, l = tid & 31;
    int g = l >> 2, t = l & 3;
    int qt = gridDim.x - 1 - blockIdx.x;      // heavy tiles first
    int qbase = qt * 128;
    int h = blockIdx.y, b = blockIdx.z;
    const size_t rs = 3 * DD;

    uint32_t sK = smem_u32(Kb);
    uint32_t sV = smem_u32(Vb);
    const uint32_t kbuf_b = 64 * VP * 4;
    const uint32_t vbuf_b = 64 * VPV * 4;

    const float* qp  = qkv + ((size_t)b * SS + qbase) * rs + h * HD;
    const float* kp0 = qkv + (size_t)b * SS * rs + DD + h * HD;

    int nkb = 2 * qt + 2;

    // K/V tile load geometry: 4 x 16B per matrix per thread (full 64x64 tile)
    int lr[4], lcc[4];
    #pragma unroll
    for (int i = 0; i < 4; i++) {
        int fid = tid + i * 256;
        lr[i]  = fid >> 4;          // 0..63
        lcc[i] = (fid & 15) << 2;   // 0..60
    }

    // prologue: prefetch K/V blocks 0 and 1
    #pragma unroll
    for (int s = 0; s < 2; s++) {
        const float* kp = kp0 + (size_t)(s * 64) * rs;
        #pragma unroll
        for (int i = 0; i < 4; i++) {
            cp_async16(sK + s * kbuf_b + (lr[i] * VP + lcc[i]) * 4,
                       kp + (size_t)lr[i] * rs + lcc[i]);
            cp_async16(sV + s * vbuf_b + (lr[i] * VPV + lcc[i]) * 4,
                       kp + DD + (size_t)lr[i] * rs + lcc[i]);
        }
        cp_commit();
    }

    // load Q tile: scale by 0.125*log2e, round to tf32
    const float QSC = 0.125f * 1.44269504088896341f;
    #pragma unroll
    for (int i = 0; i < 8; i++) {
        int fid = tid + i * 256;
        int r = fid >> 4;
        int c = (fid & 15) << 2;
        float4 q4 = *(const float4*)&qp[(size_t)r * rs + c];
        uint32_t* d = &Qs[r * VP + c];
        d[0] = f2tf32(q4.x * QSC);
        d[1] = f2tf32(q4.y * QSC);
        d[2] = f2tf32(q4.z * QSC);
        d[3] = f2tf32(q4.w * QSC);
    }
    __syncthreads();

    // preload Q A-fragments (rows 16w+g, 16w+g+8)
    int rl0 = 16 * w + g;
    uint32_t aQ[8][4];
    #pragma unroll
    for (int kt = 0; kt < 8; kt++) {
        aQ[kt][0] = Qs[rl0 * VP + 8 * kt + t];
        aQ[kt][1] = Qs[(rl0 + 8) * VP + 8 * kt + t];
        aQ[kt][2] = Qs[rl0 * VP + 8 * kt + t + 4];
        aQ[kt][3] = Qs[(rl0 + 8) * VP + 8 * kt + t + 4];
    }

    float O[8][4] = {};
    float m0 = -1e30f, m1 = -1e30f, l0 = 0.0f, l1 = 0.0f;
    int row0 = qbase + rl0;
    int row1 = row0 + 8;
    uint32_t* Pp = Qs;   // P overlays Q region (Q already in regs)

    for (int kb = 0; kb < nkb; kb++) {
        cp_wait<1>();
        __syncthreads();

        const uint32_t* Ks = Kb + (kb & 1) * 64 * VP;
        const uint32_t* Vs = Vb + (kb & 1) * 64 * VPV;

        // S(log2) = (Q*scale) @ K^T, 16x64 per warp
        float s[8][4] = {};
        #pragma unroll
        for (int kt = 0; kt < 8; kt++) {
            #pragma unroll
            for (int nt = 0; nt < 8; nt++) {
                uint32_t bf[2];
                bf[0] = Ks[(8 * nt + g) * VP + 8 * kt + t];
                bf[1] = Ks[(8 * nt + g) * VP + 8 * kt + t + 4];
                mma_tf32(s[nt], aQ[kt], bf);
            }
        }

        // causal mask
        if (kb * 64 + 63 > row0) {
            #pragma unroll
            for (int nt = 0; nt < 8; nt++) {
                int jg = kb * 64 + 8 * nt + 2 * t;
                if (jg     > row0) s[nt][0] = -1e30f;
                if (jg + 1 > row0) s[nt][1] = -1e30f;
                if (jg     > row1) s[nt][2] = -1e30f;
                if (jg + 1 > row1) s[nt][3] = -1e30f;
            }
        }

        // row max (log2 domain)
        float mx0 = -1e30f, mx1 = -1e30f;
        #pragma unroll
        for (int nt = 0; nt < 8; nt++) {
            mx0 = fmaxf(mx0, fmaxf(s[nt][0], s[nt][1]));
            mx1 = fmaxf(mx1, fmaxf(s[nt][2], s[nt][3]));
        }
        mx0 = fmaxf(mx0, __shfl_xor_sync(0xFFFFFFFF, mx0, 1));
        mx0 = fmaxf(mx0, __shfl_xor_sync(0xFFFFFFFF, mx0, 2));
        mx1 = fmaxf(mx1, __shfl_xor_sync(0xFFFFFFFF, mx1, 1));
        mx1 = fmaxf(mx1, __shfl_xor_sync(0xFFFFFFFF, mx1, 2));

        float mn0 = fmaxf(m0, mx0), mn1 = fmaxf(m1, mx1);
        float al0 = ex2f(m0 - mn0), al1 = ex2f(m1 - mn1);
        m0 = mn0; m1 = mn1;

        // P = exp2(S - m): store tf32 to Pp, accumulate row sums
        float sum0 = 0.0f, sum1 = 0.0f;
        #pragma unroll
        for (int nt = 0; nt < 8; nt++) {
            float p0 = ex2f(s[nt][0] - mn0);
            float p1 = ex2f(s[nt][1] - mn0);
            float p2 = ex2f(s[nt][2] - mn1);
            float p3 = ex2f(s[nt][3] - mn1);
            sum0 += p0 + p1;
            sum1 += p2 + p3;
            uint2 u0; u0.x = f2tf32(p0); u0.y = f2tf32(p1);
            *(uint2*)&Pp[rl0 * VP + 8 * nt + 2 * t] = u0;
            uint2 u1; u1.x = f2tf32(p2); u1.y = f2tf32(p3);
            *(uint2*)&Pp[(rl0 + 8) * VP + 8 * nt + 2 * t] = u1;
        }
        sum0 += __shfl_xor_sync(0xFFFFFFFF, sum0, 1);
        sum0 += __shfl_xor_sync(0xFFFFFFFF, sum0, 2);
        sum1 += __shfl_xor_sync(0xFFFFFFFF, sum1, 1);
        sum1 += __shfl_xor_sync(0xFFFFFFFF, sum1, 2);
        l0 = l0 * al0 + sum0;
        l1 = l1 * al1 + sum1;

        // rescale O
        #pragma unroll
        for (int nt = 0; nt < 8; nt++) {
            O[nt][0] *= al0; O[nt][1] *= al0;
            O[nt][2] *= al1; O[nt][3] *= al1;
        }
        __syncwarp();   // P visible within warp (warp-private rows)

        // O += P @ V   (V row-layout [j][d], stride VPV)
        #pragma unroll
        for (int kt = 0; kt < 8; kt++) {
            uint32_t aP[4];
            aP[0] = Pp[rl0 * VP + 8 * kt + t];
            aP[1] = Pp[(rl0 + 8) * VP + 8 * kt + t];
            aP[2] = Pp[rl0 * VP + 8 * kt + t + 4];
            aP[3] = Pp[(rl0 + 8) * VP + 8 * kt + t + 4];
            #pragma unroll
            for (int nt = 0; nt < 8; nt++) {
                uint32_t bf[2];
                bf[0] = Vs[(8 * kt + t) * VPV + 8 * nt + g];
                bf[1] = Vs[(8 * kt + t + 4) * VPV + 8 * nt + g];
                mma_tf32(O[nt], aP, bf);
            }
        }
        __syncthreads();   // all warps done reading this buffer + P

        // prefetch block kb+2 into this buffer
        if (kb + 2 < nkb) {
            const float* kp = kp0 + (size_t)((kb + 2) * 64) * rs;
            #pragma unroll
            for (int i = 0; i < 4; i++) {
                cp_async16(sK + (kb & 1) * kbuf_b + (lr[i] * VP + lcc[i]) * 4,
                           kp + (size_t)lr[i] * rs + lcc[i]);
                cp_async16(sV + (kb & 1) * vbuf_b + (lr[i] * VPV + lcc[i]) * 4,
                           kp + DD + (size_t)lr[i] * rs + lcc[i]);
            }
        }
        cp_commit();
    }

    // finalize; write tf32-rounded (consumed by proj GEMM)
    float i0 = 1.0f / l0, i1 = 1.0f / l1;
    float* op = out + (size_t)b * SS * DD + h * HD;
    #pragma unroll
    for (int nt = 0; nt < 8; nt++) {
        int c = 8 * nt + 2 * t;
        float2 o0;
        o0.x = __uint_as_float(f2tf32(O[nt][0] * i0));
        o0.y = __uint_as_float(f2tf32(O[nt][1] * i0));
        *(float2*)&op[(size_t)row0 * DD + c] = o0;
        float2 o1;
        o1.x = __uint_as_float(f2tf32(O[nt][2] * i1));
        o1.y = __uint_as_float(f2tf32(O[nt][3] * i1));
        *(float2*)&op[(size_t)row1 * DD + c] = o1;
    }
}

// ===========================================================================
// Launch
// ===========================================================================
extern "C" void kernel_launch(void* const* d_in, const int* in_sizes, int n_in,
                              void* d_out, int out_size)
{
    const float* x     = (const float*)d_in[0];
    const float* Wqkv  = (const float*)d_in[1];
    const float* bqkv  = (const float*)d_in[2];
    const float* Wproj = (const float*)d_in[3];
    const float* bproj = (const float*)d_in[4];
    float* out = (float*)d_out;

    float *qkv, *att, *wqkvT, *wprojT, *xcvt;
    cudaGetSymbolAddress((void**)&qkv, g_qkv);
    cudaGetSymbolAddress((void**)&att, g_att);
    cudaGetSymbolAddress((void**)&wqkvT, g_wqkvT);
    cudaGetSymbolAddress((void**)&wprojT, g_wprojT);
    cudaGetSymbolAddress((void**)&xcvt, g_xcvt);

    // 0) pre-round operands to tf32
    cvt_tf32_kernel<<<(MTOT * DD) / (256 * 4), 256>>>(x, xcvt);
    transpose_kernel<<<dim3(3 * DD / 32, DD / 32), dim3(32, 8)>>>(
        Wqkv, wqkvT, DD, 3 * DD);
    transpose_kernel<<<dim3(DD / 32, DD / 32), dim3(32, 8)>>>(
        Wproj, wprojT, DD, DD);

    // 1) QKV projection (pipelined tf32 mma.sync), output tf32-rounded
    gemm_mma_kernel<<<dim3(3 * DD / 128, MTOT / 128), 256>>>(
        xcvt, wqkvT, bqkv, qkv, MTOT, 3 * DD, DD, 1);

    // 2) causal flash attention (tf32 mma.sync), output tf32-rounded
    size_t smem_attn =
        (size_t)(128 * VP + 2 * 64 * VP + 2 * 64 * VPV) * sizeof(uint32_t);
    cudaFuncSetAttribute(attn_mma_kernel,
                         cudaFuncAttributeMaxDynamicSharedMemorySize,
                         (int)smem_attn);
    attn_mma_kernel<<<dim3(SS / 128, HH, BB), 256, smem_attn>>>(qkv, att);

    // 3) output projection (pipelined tf32 mma.sync), fp32 output
    gemm_mma_kernel<<<dim3(DD / 128, MTOT / 128), 256>>>(
        att, wprojT, bproj, out, MTOT, DD, DD, 0);
}

// round 8
// speedup vs baseline: 4.8930x; 1.0690x over previous
#include <cuda_runtime.h>
#include <cuda_bf16.h>
#include <math.h>
#include <stdint.h>

// Problem constants
#define BB 2
#define SS 2048
#define DD 1024
#define HH 16
#define HD 64
#define MTOT (BB*SS)       // 4096

// Scratch (allocation-free rule: __device__ globals)
__device__ float g_qkv[(size_t)BB*SS*3*DD];     // [B,S,3D] tf32-rounded
__device__ float g_att[(size_t)BB*SS*DD];       // [B,S,D]  tf32-rounded
__device__ float g_wqkvT[(size_t)3*DD*DD];      // [3D, D]  tf32-rounded
__device__ float g_wprojT[(size_t)DD*DD];       // [D, D]   tf32-rounded
__device__ float g_xcvt[(size_t)MTOT*DD];       // [B,S,D]  tf32-rounded

// ===========================================================================
// helpers
// ===========================================================================
__device__ __forceinline__ uint32_t f2tf32(float f) {
    uint32_t u;
    asm("cvt.rna.tf32.f32 %0, %1;" : "=r"(u) : "f"(f));
    return u;
}
__device__ __forceinline__ float ex2f(float x) {
    float r;
    asm("ex2.approx.ftz.f32 %0, %1;" : "=f"(r) : "f"(x));
    return r;
}
__device__ __forceinline__ void mma_tf32(float* d, const uint32_t* a,
                                         const uint32_t* b) {
    asm volatile(
        "mma.sync.aligned.m16n8k8.row.col.f32.tf32.tf32.f32 "
        "{%0,%1,%2,%3}, {%4,%5,%6,%7}, {%8,%9}, {%0,%1,%2,%3};"
        : "+f"(d[0]), "+f"(d[1]), "+f"(d[2]), "+f"(d[3])
        : "r"(a[0]), "r"(a[1]), "r"(a[2]), "r"(a[3]), "r"(b[0]), "r"(b[1]));
}
// ldmatrix x4: thread i provides the address of row (i%8) of matrix (i/8).
// For tf32, one 32-bit word == one b16 pair; lane 4g+t of each matrix
// receives (row g, word t) -> exactly the m16n8k8 tf32 fragment layout.
__device__ __forceinline__ void ldsm_x4(uint32_t* r, uint32_t addr) {
    asm volatile(
        "ldmatrix.sync.aligned.m8n8.x4.shared.b16 {%0,%1,%2,%3}, [%4];"
        : "=r"(r[0]), "=r"(r[1]), "=r"(r[2]), "=r"(r[3]) : "r"(addr));
}
__device__ __forceinline__ uint32_t smem_u32(const void* p) {
    uint32_t a;
    asm("{ .reg .u64 t; cvta.to.shared.u64 t, %1; cvt.u32.u64 %0, t; }"
        : "=r"(a) : "l"(p));
    return a;
}
__device__ __forceinline__ void cp_async16(uint32_t dst, const void* src) {
    asm volatile("cp.async.cg.shared.global [%0], [%1], 16;"
                 :: "r"(dst), "l"(src));
}
__device__ __forceinline__ void cp_commit() {
    asm volatile("cp.async.commit_group;" ::: "memory");
}
template<int N> __device__ __forceinline__ void cp_wait() {
    asm volatile("cp.async.wait_group %0;" :: "n"(N) : "memory");
}

// ===========================================================================
// x -> tf32-rounded copy
// ===========================================================================
__global__ __launch_bounds__(256) void cvt_tf32_kernel(
    const float* __restrict__ in, float* __restrict__ out)
{
    size_t i = ((size_t)blockIdx.x * 256 + threadIdx.x) * 4;
    float4 v = *(const float4*)&in[i];
    uint4 u;
    u.x = f2tf32(v.x); u.y = f2tf32(v.y);
    u.z = f2tf32(v.z); u.w = f2tf32(v.w);
    *(uint4*)&out[i] = u;
}

// ===========================================================================
// Weight transpose + tf32 round: in[R,C] -> out[C,R]
// ===========================================================================
__global__ __launch_bounds__(256) void transpose_kernel(
    const float* __restrict__ in, float* __restrict__ out, int R, int C)
{
    __shared__ float t[32][33];
    int x0 = blockIdx.x * 32;
    int y0 = blockIdx.y * 32;
    int lx = threadIdx.x, ly = threadIdx.y;
    #pragma unroll
    for (int j = 0; j < 4; j++) {
        int r = ly + j * 8;
        t[r][lx] = in[(size_t)(y0 + r) * C + x0 + lx];
    }
    __syncthreads();
    #pragma unroll
    for (int j = 0; j < 4; j++) {
        int a = ly + j * 8;
        out[(size_t)(x0 + a) * R + y0 + lx] =
            __uint_as_float(f2tf32(t[lx][a]));
    }
}

// ===========================================================================
// tf32 mma.sync GEMM, cp.async 3-stage pipeline, ldmatrix frags, 2 CTAs/SM.
// C[M,N] = A[M,K] @ Bt[N,K]^T + bias[N].  A/Bt are PRE-ROUNDED tf32 bits.
// ===========================================================================
#define BK 32
#define NSTG 3
// word index for 4-aligned word group w of row r (XOR swizzle)
#define SWW4(r, w) (((r) << 5) + (((((w) >> 2) ^ ((r) & 7))) << 2))
#define SWW(r, w)  (SWW4(r, (w) & ~3) + ((w) & 3))

__global__ __launch_bounds__(256, 2) void gemm_mma_kernel(
    const float* __restrict__ A, const float* __restrict__ Bt,
    const float* __restrict__ bias, float* __restrict__ C,
    int M, int N, int K, int cvt_out)
{
    __shared__ uint32_t As[NSTG][128 * BK];
    __shared__ uint32_t Bs[NSTG][128 * BK];
    __shared__ float    bias_s[128];

    int tid = threadIdx.x;
    int wid = tid >> 5;
    int lane = tid & 31;
    int wm = wid & 3;
    int wn = wid >> 2;
    int g = lane >> 2;
    int t = lane & 3;
    int m0 = blockIdx.y * 128;
    int n0 = blockIdx.x * 128;
    int nchunk = K / BK;

    // ldmatrix lane geometry
    int sel = lane >> 3;            // matrix id 0..3
    int lr8 = lane & 7;             // row within matrix
    int arow_off = (sel & 1) * 8 + lr8;   // A: sel&1 = row-block, sel>>1 = word-half
    int awsel    = (sel >> 1) * 4;
    int brow_off = (sel >> 1) * 8 + lr8;  // B: sel>>1 = n-block, sel&1 = word-half
    int bwsel    = (sel & 1) * 4;

    if (tid < 128) bias_s[tid] = bias[n0 + tid];

    // per-thread load geometry: 4 x 16B per matrix per chunk
    int lrow[4], lwoff[4], lc4[4];
    #pragma unroll
    for (int i = 0; i < 4; i++) {
        int u = tid + i * 256;
        int row = u >> 3;
        int c4  = u & 7;
        lrow[i] = row;
        lwoff[i] = (row << 5) + ((c4 ^ (row & 7)) << 2);
        lc4[i] = c4 * 4;
    }

    uint32_t sA = smem_u32(&As[0][0]);
    uint32_t sB = smem_u32(&Bs[0][0]);
    const uint32_t stg_bytes = 128 * BK * 4;

    #pragma unroll
    for (int s = 0; s < NSTG - 1; s++) {
        int k0 = s * BK;
        #pragma unroll
        for (int i = 0; i < 4; i++) {
            cp_async16(sA + s * stg_bytes + lwoff[i] * 4,
                       &A[(size_t)(m0 + lrow[i]) * K + k0 + lc4[i]]);
            cp_async16(sB + s * stg_bytes + lwoff[i] * 4,
                       &Bt[(size_t)(n0 + lrow[i]) * K + k0 + lc4[i]]);
        }
        cp_commit();
    }

    float acc[2][8][4] = {};

    for (int c = 0; c < nchunk; c++) {
        cp_wait<NSTG - 2>();
        __syncthreads();

        int cn = c + NSTG - 1;
        if (cn < nchunk) {
            int st = cn % NSTG;
            int k0 = cn * BK;
            #pragma unroll
            for (int i = 0; i < 4; i++) {
                cp_async16(sA + st * stg_bytes + lwoff[i] * 4,
                           &A[(size_t)(m0 + lrow[i]) * K + k0 + lc4[i]]);
                cp_async16(sB + st * stg_bytes + lwoff[i] * 4,
                           &Bt[(size_t)(n0 + lrow[i]) * K + k0 + lc4[i]]);
            }
        }
        cp_commit();

        uint32_t aBase = sA + (c % NSTG) * stg_bytes;
        uint32_t bBase = sB + (c % NSTG) * stg_bytes;
        #pragma unroll
        for (int ks = 0; ks < 4; ks++) {
            uint32_t af[2][4];
            #pragma unroll
            for (int mt = 0; mt < 2; mt++) {
                int row = wm * 32 + mt * 16 + arow_off;
                ldsm_x4(af[mt], aBase + SWW4(row, 8 * ks + awsel) * 4);
            }
            uint32_t bf[4][4];
            #pragma unroll
            for (int ntp = 0; ntp < 4; ntp++) {
                int row = wn * 64 + ntp * 16 + brow_off;
                ldsm_x4(bf[ntp], bBase + SWW4(row, 8 * ks + bwsel) * 4);
            }
            #pragma unroll
            for (int mt = 0; mt < 2; mt++)
                #pragma unroll
                for (int ntp = 0; ntp < 4; ntp++) {
                    mma_tf32(acc[mt][2 * ntp],     af[mt], &bf[ntp][0]);
                    mma_tf32(acc[mt][2 * ntp + 1], af[mt], &bf[ntp][2]);
                }
        }
    }

    #pragma unroll
    for (int mt = 0; mt < 2; mt++) {
        int r0 = m0 + wm * 32 + mt * 16 + g;
        #pragma unroll
        for (int nt = 0; nt < 8; nt++) {
            int cl = wn * 64 + nt * 8 + 2 * t;
            int cc = n0 + cl;
            float v00 = acc[mt][nt][0] + bias_s[cl];
            float v01 = acc[mt][nt][1] + bias_s[cl + 1];
            float v10 = acc[mt][nt][2] + bias_s[cl];
            float v11 = acc[mt][nt][3] + bias_s[cl + 1];
            float2 v0, v1;
            if (cvt_out) {
                v0.x = __uint_as_float(f2tf32(v00));
                v0.y = __uint_as_float(f2tf32(v01));
                v1.x = __uint_as_float(f2tf32(v10));
                v1.y = __uint_as_float(f2tf32(v11));
            } else {
                v0.x = v00; v0.y = v01; v1.x = v10; v1.y = v11;
            }
            *(float2*)&C[(size_t)r0 * N + cc] = v0;
            *(float2*)&C[(size_t)(r0 + 8) * N + cc] = v1;
        }
    }
}

// ===========================================================================
// Tensor-core flash attention (tf32 mma.sync, causal), cp.async K/V pipeline,
// ldmatrix for Q/K/P fragments. V fragments stay scalar (needs 32-bit
// transpose that ldmatrix.b16 can't do); VPV=72 keeps them conflict-free.
// ===========================================================================
#define VP  68
#define VPV 72

__global__ __launch_bounds__(256, 2) void attn_mma_kernel(
    const float* __restrict__ qkv, float* __restrict__ out)
{
    extern __shared__ uint32_t smu[];
    uint32_t* Qs = smu;                       // 128*VP (later: P buffer)
    uint32_t* Kb = Qs + 128 * VP;             // 2 x 64*VP
    uint32_t* Vb = Kb + 2 * 64 * VP;          // 2 x 64*VPV

    int tid = threadIdx.x;
    int w = tid >> 5, l = tid & 31;
    int g = l >> 2, t = l & 3;
    int qt = gridDim.x - 1 - blockIdx.x;      // heavy tiles first
    int qbase = qt * 128;
    int h = blockIdx.y, b = blockIdx.z;
    const size_t rs = 3 * DD;

    // ldmatrix lane geometry
    int sel = l >> 3;
    int lr8 = l & 7;
    int arow_off = (sel & 1) * 8 + lr8;   // A-operand (Q, P)
    int awsel    = (sel >> 1) * 4;
    int brow_off = (sel >> 1) * 8 + lr8;  // B-operand (K)
    int bwsel    = (sel & 1) * 4;

    uint32_t sQ = smem_u32(Qs);
    uint32_t sK = smem_u32(Kb);
    uint32_t sV = smem_u32(Vb);
    const uint32_t kbuf_b = 64 * VP * 4;
    const uint32_t vbuf_b = 64 * VPV * 4;

    const float* qp  = qkv + ((size_t)b * SS + qbase) * rs + h * HD;
    const float* kp0 = qkv + (size_t)b * SS * rs + DD + h * HD;

    int nkb = 2 * qt + 2;

    // K/V tile load geometry: 4 x 16B per matrix per thread (full 64x64 tile)
    int lr[4], lcc[4];
    #pragma unroll
    for (int i = 0; i < 4; i++) {
        int fid = tid + i * 256;
        lr[i]  = fid >> 4;          // 0..63
        lcc[i] = (fid & 15) << 2;   // 0..60
    }

    // prologue: prefetch K/V blocks 0 and 1
    #pragma unroll
    for (int s = 0; s < 2; s++) {
        const float* kp = kp0 + (size_t)(s * 64) * rs;
        #pragma unroll
        for (int i = 0; i < 4; i++) {
            cp_async16(sK + s * kbuf_b + (lr[i] * VP + lcc[i]) * 4,
                       kp + (size_t)lr[i] * rs + lcc[i]);
            cp_async16(sV + s * vbuf_b + (lr[i] * VPV + lcc[i]) * 4,
                       kp + DD + (size_t)lr[i] * rs + lcc[i]);
        }
        cp_commit();
    }

    // load Q tile: scale by 0.125*log2e, round to tf32
    const float QSC = 0.125f * 1.44269504088896341f;
    #pragma unroll
    for (int i = 0; i < 8; i++) {
        int fid = tid + i * 256;
        int r = fid >> 4;
        int c = (fid & 15) << 2;
        float4 q4 = *(const float4*)&qp[(size_t)r * rs + c];
        uint32_t* d = &Qs[r * VP + c];
        d[0] = f2tf32(q4.x * QSC);
        d[1] = f2tf32(q4.y * QSC);
        d[2] = f2tf32(q4.z * QSC);
        d[3] = f2tf32(q4.w * QSC);
    }
    __syncthreads();

    // preload Q A-fragments via ldmatrix (rows 16w..16w+15)
    int rl0 = 16 * w + g;
    uint32_t aQ[8][4];
    #pragma unroll
    for (int kt = 0; kt < 8; kt++)
        ldsm_x4(aQ[kt],
                sQ + ((16 * w + arow_off) * VP + 8 * kt + awsel) * 4);

    float O[8][4] = {};
    float m0 = -1e30f, m1 = -1e30f, l0 = 0.0f, l1 = 0.0f;
    int row0 = qbase + rl0;
    int row1 = row0 + 8;
    uint32_t* Pp = Qs;   // P overlays Q region (Q already in regs)

    for (int kb = 0; kb < nkb; kb++) {
        cp_wait<1>();
        __syncthreads();

        uint32_t kBase = sK + (kb & 1) * kbuf_b;
        const uint32_t* Vs = Vb + (kb & 1) * 64 * VPV;

        // S(log2) = (Q*scale) @ K^T, 16x64 per warp
        float s[8][4] = {};
        #pragma unroll
        for (int kt = 0; kt < 8; kt++) {
            #pragma unroll
            for (int ntp = 0; ntp < 4; ntp++) {
                uint32_t kf[4];
                ldsm_x4(kf, kBase +
                        ((ntp * 16 + brow_off) * VP + 8 * kt + bwsel) * 4);
                mma_tf32(s[2 * ntp],     aQ[kt], &kf[0]);
                mma_tf32(s[2 * ntp + 1], aQ[kt], &kf[2]);
            }
        }

        // causal mask
        if (kb * 64 + 63 > row0) {
            #pragma unroll
            for (int nt = 0; nt < 8; nt++) {
                int jg = kb * 64 + 8 * nt + 2 * t;
                if (jg     > row0) s[nt][0] = -1e30f;
                if (jg + 1 > row0) s[nt][1] = -1e30f;
                if (jg     > row1) s[nt][2] = -1e30f;
                if (jg + 1 > row1) s[nt][3] = -1e30f;
            }
        }

        // row max (log2 domain)
        float mx0 = -1e30f, mx1 = -1e30f;
        #pragma unroll
        for (int nt = 0; nt < 8; nt++) {
            mx0 = fmaxf(mx0, fmaxf(s[nt][0], s[nt][1]));
            mx1 = fmaxf(mx1, fmaxf(s[nt][2], s[nt][3]));
        }
        mx0 = fmaxf(mx0, __shfl_xor_sync(0xFFFFFFFF, mx0, 1));
        mx0 = fmaxf(mx0, __shfl_xor_sync(0xFFFFFFFF, mx0, 2));
        mx1 = fmaxf(mx1, __shfl_xor_sync(0xFFFFFFFF, mx1, 1));
        mx1 = fmaxf(mx1, __shfl_xor_sync(0xFFFFFFFF, mx1, 2));

        float mn0 = fmaxf(m0, mx0), mn1 = fmaxf(m1, mx1);
        float al0 = ex2f(m0 - mn0), al1 = ex2f(m1 - mn1);
        m0 = mn0; m1 = mn1;

        // P = exp2(S - m): store tf32 to Pp, accumulate row sums
        float sum0 = 0.0f, sum1 = 0.0f;
        #pragma unroll
        for (int nt = 0; nt < 8; nt++) {
            float p0 = ex2f(s[nt][0] - mn0);
            float p1 = ex2f(s[nt][1] - mn0);
            float p2 = ex2f(s[nt][2] - mn1);
            float p3 = ex2f(s[nt][3] - mn1);
            sum0 += p0 + p1;
            sum1 += p2 + p3;
            uint2 u0; u0.x = f2tf32(p0); u0.y = f2tf32(p1);
            *(uint2*)&Pp[rl0 * VP + 8 * nt + 2 * t] = u0;
            uint2 u1; u1.x = f2tf32(p2); u1.y = f2tf32(p3);
            *(uint2*)&Pp[(rl0 + 8) * VP + 8 * nt + 2 * t] = u1;
        }
        sum0 += __shfl_xor_sync(0xFFFFFFFF, sum0, 1);
        sum0 += __shfl_xor_sync(0xFFFFFFFF, sum0, 2);
        sum1 += __shfl_xor_sync(0xFFFFFFFF, sum1, 1);
        sum1 += __shfl_xor_sync(0xFFFFFFFF, sum1, 2);
        l0 = l0 * al0 + sum0;
        l1 = l1 * al1 + sum1;

        // rescale O
        #pragma unroll
        for (int nt = 0; nt < 8; nt++) {
            O[nt][0] *= al0; O[nt][1] *= al0;
            O[nt][2] *= al1; O[nt][3] *= al1;
        }
        __syncwarp();   // P visible within warp (warp-private rows)

        // O += P @ V   (P frags via ldmatrix; V row-layout [j][d], scalar)
        #pragma unroll
        for (int kt = 0; kt < 8; kt++) {
            uint32_t aP[4];
            ldsm_x4(aP, sQ + ((16 * w + arow_off) * VP + 8 * kt + awsel) * 4);
            #pragma unroll
            for (int nt = 0; nt < 8; nt++) {
                uint32_t bf[2];
                bf[0] = Vs[(8 * kt + t) * VPV + 8 * nt + g];
                bf[1] = Vs[(8 * kt + t + 4) * VPV + 8 * nt + g];
                mma_tf32(O[nt], aP, bf);
            }
        }
        __syncthreads();   // all warps done reading this buffer + P

        // prefetch block kb+2 into this buffer
        if (kb + 2 < nkb) {
            const float* kp = kp0 + (size_t)((kb + 2) * 64) * rs;
            #pragma unroll
            for (int i = 0; i < 4; i++) {
                cp_async16(sK + (kb & 1) * kbuf_b + (lr[i] * VP + lcc[i]) * 4,
                           kp + (size_t)lr[i] * rs + lcc[i]);
                cp_async16(sV + (kb & 1) * vbuf_b + (lr[i] * VPV + lcc[i]) * 4,
                           kp + DD + (size_t)lr[i] * rs + lcc[i]);
            }
        }
        cp_commit();
    }

    // finalize; write tf32-rounded (consumed by proj GEMM)
    float i0 = 1.0f / l0, i1 = 1.0f / l1;
    float* op = out + (size_t)b * SS * DD + h * HD;
    #pragma unroll
    for (int nt = 0; nt < 8; nt++) {
        int c = 8 * nt + 2 * t;
        float2 o0;
        o0.x = __uint_as_float(f2tf32(O[nt][0] * i0));
        o0.y = __uint_as_float(f2tf32(O[nt][1] * i0));
        *(float2*)&op[(size_t)row0 * DD + c] = o0;
        float2 o1;
        o1.x = __uint_as_float(f2tf32(O[nt][2] * i1));
        o1.y = __uint_as_float(f2tf32(O[nt][3] * i1));
        *(float2*)&op[(size_t)row1 * DD + c] = o1;
    }
}

// ===========================================================================
// Launch
// ===========================================================================
extern "C" void kernel_launch(void* const* d_in, const int* in_sizes, int n_in,
                              void* d_out, int out_size)
{
    const float* x     = (const float*)d_in[0];
    const float* Wqkv  = (const float*)d_in[1];
    const float* bqkv  = (const float*)d_in[2];
    const float* Wproj = (const float*)d_in[3];
    const float* bproj = (const float*)d_in[4];
    float* out = (float*)d_out;

    float *qkv, *att, *wqkvT, *wprojT, *xcvt;
    cudaGetSymbolAddress((void**)&qkv, g_qkv);
    cudaGetSymbolAddress((void**)&att, g_att);
    cudaGetSymbolAddress((void**)&wqkvT, g_wqkvT);
    cudaGetSymbolAddress((void**)&wprojT, g_wprojT);
    cudaGetSymbolAddress((void**)&xcvt, g_xcvt);

    // 0) pre-round operands to tf32
    cvt_tf32_kernel<<<(MTOT * DD) / (256 * 4), 256>>>(x, xcvt);
    transpose_kernel<<<dim3(3 * DD / 32, DD / 32), dim3(32, 8)>>>(
        Wqkv, wqkvT, DD, 3 * DD);
    transpose_kernel<<<dim3(DD / 32, DD / 32), dim3(32, 8)>>>(
        Wproj, wprojT, DD, DD);

    // 1) QKV projection (pipelined tf32 mma.sync), output tf32-rounded
    gemm_mma_kernel<<<dim3(3 * DD / 128, MTOT / 128), 256>>>(
        xcvt, wqkvT, bqkv, qkv, MTOT, 3 * DD, DD, 1);

    // 2) causal flash attention (tf32 mma.sync), output tf32-rounded
    size_t smem_attn =
        (size_t)(128 * VP + 2 * 64 * VP + 2 * 64 * VPV) * sizeof(uint32_t);
    cudaFuncSetAttribute(attn_mma_kernel,
                         cudaFuncAttributeMaxDynamicSharedMemorySize,
                         (int)smem_attn);
    attn_mma_kernel<<<dim3(SS / 128, HH, BB), 256, smem_attn>>>(qkv, att);

    // 3) output projection (pipelined tf32 mma.sync), fp32 output
    gemm_mma_kernel<<<dim3(DD / 128, MTOT / 128), 256>>>(
        att, wprojT, bproj, out, MTOT, DD, DD, 0);
}